// round 4
// baseline (speedup 1.0000x reference)
#include <cuda_runtime.h>
#include <cuda_bf16.h>
#include <cstdint>
#include <cstddef>

#define NN 50000
#define NE 800000

// ---------------- scratch (no allocation allowed) ----------------
__device__ float g_agg[NN * 256];     // segment-sum of edge_feat
__device__ float g_cagg[NN * 4];      // {sum dx*phi, dy*phi, dz*phi, count}
__device__ float g_hr[NN * 256];      // tf32-rounded copy of h
__device__ float g_We1t[513 * 256];   // transposed + tf32-rounded weights [k][n]
__device__ float g_We2t[256 * 256];
__device__ float g_Wc1t[256 * 256];
__device__ float g_Wn1t[512 * 256];
__device__ float g_Wn2t[256 * 256];

// ---------------- smem layout (bytes) ----------------
#define OFF_A1   0         // 2 x 128 x 20 floats  = 20480 B
#define OFF_B    20480     // 2 x 16 x 264 floats  = 33792 B
#define OFF_A2   54272     // 128 x 260 floats     = 133120 B
#define OFF_RS   187392    // 128 ints
#define OFF_CS   187904    // 128 ints
#define OFF_CD   188416    // 128 float4
#define OFF_PHI  190464    // 128 floats
#define OFF_BIAS 190976    // 3 x 256 floats
#define OFF_W512 194048    // 256 floats
#define OFF_WC2  195072    // 256 floats
#define SMEM_BYTES 196096

// ---------------- helpers ----------------
__device__ __forceinline__ uint32_t smem_u32(const void* p) {
    uint32_t a;
    asm("{ .reg .u64 t; cvta.to.shared.u64 t, %1; cvt.u32.u64 %0, t; }" : "=r"(a) : "l"(p));
    return a;
}
__device__ __forceinline__ void cpa16(uint32_t s, const void* g) {
    asm volatile("cp.async.cg.shared.global [%0], [%1], 16;" :: "r"(s), "l"(g));
}
__device__ __forceinline__ void cpcommit() { asm volatile("cp.async.commit_group;"); }

// cvt.rna.tf32.f32 requires a .b32 destination register.
__device__ __forceinline__ float to_tf32(float x) {
    uint32_t y;
    asm("cvt.rna.tf32.f32 %0, %1;" : "=r"(y) : "f"(x));
    return __uint_as_float(y);
}
__device__ __forceinline__ float silu_f(float x) {
    return x / (1.0f + __expf(-x));
}
__device__ __forceinline__ void red4(float* gp, float x, float y, float z, float w) {
    asm volatile("red.global.add.v4.f32 [%0], {%1,%2,%3,%4};"
                 :: "l"(gp), "f"(x), "f"(y), "f"(z), "f"(w) : "memory");
}

// One K=16 chunk of the warp-tiled GEMM. Warp tile 64x64 (4 m-frags x 8 n-frags),
// mma m16n8k8 tf32. A smem stride SA floats (20 or 260), B stride 264.
template <int SA>
__device__ __forceinline__ void gemm_chunk(const float* __restrict__ Ac,
                                           const float* __restrict__ Bc,
                                           float (&c)[4][8][4],
                                           int wm, int wn, int g, int t) {
#pragma unroll
    for (int k8 = 0; k8 < 16; k8 += 8) {
        uint32_t a[4][4];
#pragma unroll
        for (int i = 0; i < 4; i++) {
            const float* ap = Ac + (wm * 64 + i * 16 + g) * SA + k8 + t;
            a[i][0] = __float_as_uint(ap[0]);
            a[i][1] = __float_as_uint(ap[8 * SA]);
            a[i][2] = __float_as_uint(ap[4]);
            a[i][3] = __float_as_uint(ap[8 * SA + 4]);
        }
        uint32_t b[8][2];
#pragma unroll
        for (int j = 0; j < 8; j++) {
            const float* bp = Bc + (k8 + t) * 264 + wn * 64 + j * 8 + g;
            b[j][0] = __float_as_uint(bp[0]);
            b[j][1] = __float_as_uint(bp[4 * 264]);
        }
#pragma unroll
        for (int i = 0; i < 4; i++)
#pragma unroll
            for (int j = 0; j < 8; j++)
                asm volatile(
                    "mma.sync.aligned.m16n8k8.row.col.f32.tf32.tf32.f32 "
                    "{%0,%1,%2,%3},{%4,%5,%6,%7},{%8,%9},{%0,%1,%2,%3};"
                    : "+f"(c[i][j][0]), "+f"(c[i][j][1]), "+f"(c[i][j][2]), "+f"(c[i][j][3])
                    : "r"(a[i][0]), "r"(a[i][1]), "r"(a[i][2]), "r"(a[i][3]),
                      "r"(b[j][0]), "r"(b[j][1]));
    }
}

__device__ __forceinline__ void init_bias(float (&c)[4][8][4], const float* bs, int wn, int t) {
#pragma unroll
    for (int j = 0; j < 8; j++) {
        int col = wn * 64 + j * 8 + 2 * t;
        float b0 = bs[col], b1 = bs[col + 1];
#pragma unroll
        for (int i = 0; i < 4; i++) {
            c[i][j][0] = b0; c[i][j][1] = b1; c[i][j][2] = b0; c[i][j][3] = b1;
        }
    }
}

// Apply SiLU, round to tf32, write to A2 (stride 260).
__device__ __forceinline__ void store_silu(const float (&c)[4][8][4], float* A2,
                                           int wm, int wn, int g, int t) {
#pragma unroll
    for (int i = 0; i < 4; i++) {
        int r0 = wm * 64 + i * 16 + g;
#pragma unroll
        for (int j = 0; j < 8; j++) {
            int col = wn * 64 + j * 8 + 2 * t;
            A2[r0 * 260 + col]           = to_tf32(silu_f(c[i][j][0]));
            A2[r0 * 260 + col + 1]       = to_tf32(silu_f(c[i][j][1]));
            A2[(r0 + 8) * 260 + col]     = to_tf32(silu_f(c[i][j][2]));
            A2[(r0 + 8) * 260 + col + 1] = to_tf32(silu_f(c[i][j][3]));
        }
    }
}

// ---------------- prep kernels ----------------
__global__ void round_h_kernel(const float* __restrict__ h) {
    int i = blockIdx.x * blockDim.x + threadIdx.x;
    if (i < NN * 256) g_hr[i] = to_tf32(h[i]);
}
__global__ void round_agg_kernel() {
    int i = blockIdx.x * blockDim.x + threadIdx.x;
    if (i < NN * 256) g_agg[i] = to_tf32(g_agg[i]);
}
__global__ void transpose_round(const float* __restrict__ W, float* __restrict__ Wt,
                                int K, int N) {
    int i = blockIdx.x * blockDim.x + threadIdx.x;
    if (i < K * N) {
        int k = i / N, n = i - k * N;
        Wt[i] = to_tf32(W[n * K + k]);
    }
}

// ---------------- edge kernel ----------------
__global__ __launch_bounds__(256, 1) void edge_kernel(
    const float* __restrict__ coordp, const int* __restrict__ ei,
    const float* __restrict__ be1, const float* __restrict__ be2,
    const float* __restrict__ bc1, const float* __restrict__ wc2) {
    extern __shared__ char smem[];
    float* A1s = (float*)(smem + OFF_A1);
    float* Bsm = (float*)(smem + OFF_B);
    float* A2  = (float*)(smem + OFF_A2);
    int* rs = (int*)(smem + OFF_RS);
    int* cs = (int*)(smem + OFF_CS);
    float4* cd = (float4*)(smem + OFF_CD);
    float* phis = (float*)(smem + OFF_PHI);
    float* b1s = (float*)(smem + OFF_BIAS);
    float* b2s = b1s + 256;
    float* b3s = b1s + 512;
    float* w512s = (float*)(smem + OFF_W512);
    float* wc2s = (float*)(smem + OFF_WC2);

    const int tid = threadIdx.x;
    const int warp = tid >> 5, lane = tid & 31;
    const int wm = warp >> 2, wn = warp & 3, g = lane >> 2, t = lane & 3;
    const int ebase = blockIdx.x * 128;
    const uint32_t sbase = smem_u32(smem);
    const uint32_t a1u = sbase + OFF_A1, bu = sbase + OFF_B;

    if (tid < 128) {
        int r = ei[ebase + tid], c = ei[NE + ebase + tid];
        rs[tid] = r; cs[tid] = c;
        float dx = coordp[r * 3 + 0] - coordp[c * 3 + 0];
        float dy = coordp[r * 3 + 1] - coordp[c * 3 + 1];
        float dz = coordp[r * 3 + 2] - coordp[c * 3 + 2];
        cd[tid] = make_float4(dx, dy, dz, dx * dx + dy * dy + dz * dz);
        phis[tid] = 0.f;
    }
    b1s[tid] = be1[tid]; b2s[tid] = be2[tid]; b3s[tid] = bc1[tid];
    w512s[tid] = g_We1t[512 * 256 + tid];
    wc2s[tid] = to_tf32(wc2[tid]);
    __syncthreads();

    float c[4][8][4];

    auto stageA1 = [&](int kc, int buf) {
        int k0 = kc * 16;
        const int* src = (k0 < 256) ? rs : cs;
        int koff = k0 & 255;
        int e = tid >> 1, half = tid & 1;
        const float* gp = g_hr + (size_t)src[e] * 256 + koff + half * 8;
        uint32_t d = a1u + (uint32_t)(buf * 2560 + e * 20 + half * 8) * 4u;
        cpa16(d, gp); cpa16(d + 16u, gp + 4);
    };
    auto stageB = [&](const float* __restrict__ gW, int kc, int buf) {
        int k0 = kc * 16;
#pragma unroll
        for (int it = 0; it < 4; it++) {
            int v = it * 256 + tid;
            int k = v >> 6, n = (v & 63) << 2;
            cpa16(bu + (uint32_t)(buf * 4224 + k * 264 + n) * 4u, gW + (size_t)(k0 + k) * 256 + n);
        }
    };

    // ---- GEMM1: [h[row] | h[col]] @ We1^T (K=512 tensor part) ----
    init_bias(c, b1s, wn, t);
    stageA1(0, 0); stageB(g_We1t, 0, 0); cpcommit();
    for (int kc = 0; kc < 32; kc++) {
        if (kc + 1 < 32) {
            stageA1(kc + 1, (kc + 1) & 1); stageB(g_We1t, kc + 1, (kc + 1) & 1);
            cpcommit();
            asm volatile("cp.async.wait_group 1;");
        } else {
            asm volatile("cp.async.wait_group 0;");
        }
        __syncthreads();
        gemm_chunk<20>(A1s + (kc & 1) * 2560, Bsm + (kc & 1) * 4224, c, wm, wn, g, t);
        __syncthreads();
    }
    // radial rank-1 tail (k = 512) in fp32
#pragma unroll
    for (int i = 0; i < 4; i++) {
        int r0 = wm * 64 + i * 16 + g;
        float ra = cd[r0].w, rb = cd[r0 + 8].w;
#pragma unroll
        for (int j = 0; j < 8; j++) {
            int col = wn * 64 + j * 8 + 2 * t;
            float w0 = w512s[col], w1 = w512s[col + 1];
            c[i][j][0] += ra * w0; c[i][j][1] += ra * w1;
            c[i][j][2] += rb * w0; c[i][j][3] += rb * w1;
        }
    }
    store_silu(c, A2, wm, wn, g, t);
    __syncthreads();
    stageB(g_We2t, 0, 0); cpcommit();

    // ---- GEMM2: m @ We2^T (K=256) ----
    init_bias(c, b2s, wn, t);
    for (int kc = 0; kc < 16; kc++) {
        if (kc + 1 < 16) {
            stageB(g_We2t, kc + 1, (kc + 1) & 1); cpcommit();
            asm volatile("cp.async.wait_group 1;");
        } else {
            asm volatile("cp.async.wait_group 0;");
        }
        __syncthreads();
        gemm_chunk<260>(A2 + kc * 16, Bsm + (kc & 1) * 4224, c, wm, wn, g, t);
        __syncthreads();
    }
    store_silu(c, A2, wm, wn, g, t);   // A2 now holds edge_feat (tf32-rounded)
    __syncthreads();
    stageB(g_Wc1t, 0, 0); cpcommit();

    // ---- GEMM3: edge_feat @ Wc1^T (K=256) ----
    init_bias(c, b3s, wn, t);
    for (int kc = 0; kc < 16; kc++) {
        if (kc + 1 < 16) {
            stageB(g_Wc1t, kc + 1, (kc + 1) & 1); cpcommit();
            asm volatile("cp.async.wait_group 1;");
        } else {
            asm volatile("cp.async.wait_group 0;");
        }
        __syncthreads();
        gemm_chunk<260>(A2 + kc * 16, Bsm + (kc & 1) * 4224, c, wm, wn, g, t);
        __syncthreads();
    }

    // phi_x[e] = silu(C3) . wc2  (fp32 dot + cross-lane + cross-warp reduce)
    {
        float pr[8];
#pragma unroll
        for (int k = 0; k < 8; k++) pr[k] = 0.f;
#pragma unroll
        for (int i = 0; i < 4; i++)
#pragma unroll
            for (int j = 0; j < 8; j++) {
                int col = wn * 64 + j * 8 + 2 * t;
                float w0 = wc2s[col], w1 = wc2s[col + 1];
                pr[i * 2]     += silu_f(c[i][j][0]) * w0 + silu_f(c[i][j][1]) * w1;
                pr[i * 2 + 1] += silu_f(c[i][j][2]) * w0 + silu_f(c[i][j][3]) * w1;
            }
#pragma unroll
        for (int k = 0; k < 8; k++) {
            pr[k] += __shfl_xor_sync(0xffffffffu, pr[k], 1);
            pr[k] += __shfl_xor_sync(0xffffffffu, pr[k], 2);
        }
        if (t == 0) {
#pragma unroll
            for (int i = 0; i < 4; i++) {
                atomicAdd(&phis[wm * 64 + i * 16 + g], pr[i * 2]);
                atomicAdd(&phis[wm * 64 + i * 16 + g + 8], pr[i * 2 + 1]);
            }
        }
    }
    __syncthreads();

    // coord aggregation: {dx,dy,dz}*phi + count, one v4 red per edge
    if (tid < 128) {
        float4 d = cd[tid];
        float p = phis[tid];
        red4(&g_cagg[(size_t)rs[tid] * 4], d.x * p, d.y * p, d.z * p, 1.0f);
    }
    // feature aggregation: edge_feat rows into g_agg[row], v4 red from smem
#pragma unroll
    for (int it = 0; it < 32; it++) {
        int v = it * 256 + tid;
        int r = v >> 6, c4 = (v & 63) << 2;
        const float* sp = A2 + r * 260 + c4;
        red4(&g_agg[(size_t)rs[r] * 256 + c4], sp[0], sp[1], sp[2], sp[3]);
    }
}

// ---------------- node kernel ----------------
__global__ __launch_bounds__(256, 1) void node_kernel(
    const float* __restrict__ h, const float* __restrict__ bn1,
    const float* __restrict__ bn2, float* __restrict__ out) {
    extern __shared__ char smem[];
    float* A1s = (float*)(smem + OFF_A1);
    float* Bsm = (float*)(smem + OFF_B);
    float* A2  = (float*)(smem + OFF_A2);
    int* idx = (int*)(smem + OFF_RS);
    float* b1s = (float*)(smem + OFF_BIAS);
    float* b2s = b1s + 256;

    const int tid = threadIdx.x;
    const int warp = tid >> 5, lane = tid & 31;
    const int wm = warp >> 2, wn = warp & 3, g = lane >> 2, t = lane & 3;
    const int base = blockIdx.x * 128;
    const uint32_t sbase = smem_u32(smem);
    const uint32_t a1u = sbase + OFF_A1, bu = sbase + OFF_B;

    if (tid < 128) {
        int n = base + tid;
        idx[tid] = (n < NN) ? n : 0;
    }
    b1s[tid] = bn1[tid]; b2s[tid] = bn2[tid];
    __syncthreads();

    float c[4][8][4];

    auto stageA = [&](int kc, int buf) {
        int k0 = kc * 16;
        const float* basep = (k0 < 256) ? g_hr : g_agg;
        int koff = k0 & 255;
        int e = tid >> 1, half = tid & 1;
        const float* gp = basep + (size_t)idx[e] * 256 + koff + half * 8;
        uint32_t d = a1u + (uint32_t)(buf * 2560 + e * 20 + half * 8) * 4u;
        cpa16(d, gp); cpa16(d + 16u, gp + 4);
    };
    auto stageB = [&](const float* __restrict__ gW, int kc, int buf) {
        int k0 = kc * 16;
#pragma unroll
        for (int it = 0; it < 4; it++) {
            int v = it * 256 + tid;
            int k = v >> 6, n = (v & 63) << 2;
            cpa16(bu + (uint32_t)(buf * 4224 + k * 264 + n) * 4u, gW + (size_t)(k0 + k) * 256 + n);
        }
    };

    // GEMM1: [h | agg] @ Wn1^T (K=512)
    init_bias(c, b1s, wn, t);
    stageA(0, 0); stageB(g_Wn1t, 0, 0); cpcommit();
    for (int kc = 0; kc < 32; kc++) {
        if (kc + 1 < 32) {
            stageA(kc + 1, (kc + 1) & 1); stageB(g_Wn1t, kc + 1, (kc + 1) & 1);
            cpcommit();
            asm volatile("cp.async.wait_group 1;");
        } else {
            asm volatile("cp.async.wait_group 0;");
        }
        __syncthreads();
        gemm_chunk<20>(A1s + (kc & 1) * 2560, Bsm + (kc & 1) * 4224, c, wm, wn, g, t);
        __syncthreads();
    }
    store_silu(c, A2, wm, wn, g, t);
    __syncthreads();
    stageB(g_Wn2t, 0, 0); cpcommit();

    // GEMM2: @ Wn2^T (K=256), + bn2 + residual h
    init_bias(c, b2s, wn, t);
    for (int kc = 0; kc < 16; kc++) {
        if (kc + 1 < 16) {
            stageB(g_Wn2t, kc + 1, (kc + 1) & 1); cpcommit();
            asm volatile("cp.async.wait_group 1;");
        } else {
            asm volatile("cp.async.wait_group 0;");
        }
        __syncthreads();
        gemm_chunk<260>(A2 + kc * 16, Bsm + (kc & 1) * 4224, c, wm, wn, g, t);
        __syncthreads();
    }
#pragma unroll
    for (int i = 0; i < 4; i++) {
        int r0 = wm * 64 + i * 16 + g;
        int n0 = base + r0, n1 = base + r0 + 8;
#pragma unroll
        for (int j = 0; j < 8; j++) {
            int col = wn * 64 + j * 8 + 2 * t;
            if (n0 < NN) {
                out[(size_t)n0 * 256 + col]     = c[i][j][0] + h[(size_t)n0 * 256 + col];
                out[(size_t)n0 * 256 + col + 1] = c[i][j][1] + h[(size_t)n0 * 256 + col + 1];
            }
            if (n1 < NN) {
                out[(size_t)n1 * 256 + col]     = c[i][j][2] + h[(size_t)n1 * 256 + col];
                out[(size_t)n1 * 256 + col + 1] = c[i][j][3] + h[(size_t)n1 * 256 + col + 1];
            }
        }
    }
}

// ---------------- coord finish ----------------
__global__ void coord_kernel(const float* __restrict__ coordp, float* __restrict__ out) {
    int n = blockIdx.x * blockDim.x + threadIdx.x;
    if (n < NN) {
        float cnt = g_cagg[n * 4 + 3];
        float s = 1.0f / fmaxf(cnt, 1.0f);
        float* o = out + (size_t)NN * 256 + (size_t)n * 3;
        o[0] = coordp[n * 3 + 0] + g_cagg[n * 4 + 0] * s;
        o[1] = coordp[n * 3 + 1] + g_cagg[n * 4 + 1] * s;
        o[2] = coordp[n * 3 + 2] + g_cagg[n * 4 + 2] * s;
    }
}

// ---------------- host ----------------
extern "C" void kernel_launch(void* const* d_in, const int* in_sizes, int n_in,
                              void* d_out, int out_size) {
    (void)in_sizes; (void)n_in; (void)out_size;
    const float* h     = (const float*)d_in[0];
    const int*   ei    = (const int*)d_in[1];
    const float* coord = (const float*)d_in[2];
    const float* We1   = (const float*)d_in[3];
    const float* be1   = (const float*)d_in[4];
    const float* We2   = (const float*)d_in[5];
    const float* be2   = (const float*)d_in[6];
    const float* Wn1   = (const float*)d_in[7];
    const float* bn1   = (const float*)d_in[8];
    const float* Wn2   = (const float*)d_in[9];
    const float* bn2   = (const float*)d_in[10];
    const float* Wc1   = (const float*)d_in[11];
    const float* bc1   = (const float*)d_in[12];
    const float* Wc2   = (const float*)d_in[13];
    float* out = (float*)d_out;

    cudaFuncSetAttribute(edge_kernel, cudaFuncAttributeMaxDynamicSharedMemorySize, SMEM_BYTES);
    cudaFuncSetAttribute(node_kernel, cudaFuncAttributeMaxDynamicSharedMemorySize, SMEM_BYTES);

    void* agg_p = nullptr; void* cagg_p = nullptr;
    cudaGetSymbolAddress(&agg_p, g_agg);
    cudaGetSymbolAddress(&cagg_p, g_cagg);
    cudaMemsetAsync(agg_p, 0, sizeof(float) * (size_t)NN * 256, 0);
    cudaMemsetAsync(cagg_p, 0, sizeof(float) * (size_t)NN * 4, 0);

    float* we1t; float* we2t; float* wc1t; float* wn1t; float* wn2t;
    cudaGetSymbolAddress((void**)&we1t, g_We1t);
    cudaGetSymbolAddress((void**)&we2t, g_We2t);
    cudaGetSymbolAddress((void**)&wc1t, g_Wc1t);
    cudaGetSymbolAddress((void**)&wn1t, g_Wn1t);
    cudaGetSymbolAddress((void**)&wn2t, g_Wn2t);

    transpose_round<<<(513 * 256 + 255) / 256, 256>>>(We1, we1t, 513, 256);
    transpose_round<<<(256 * 256 + 255) / 256, 256>>>(We2, we2t, 256, 256);
    transpose_round<<<(256 * 256 + 255) / 256, 256>>>(Wc1, wc1t, 256, 256);
    transpose_round<<<(512 * 256 + 255) / 256, 256>>>(Wn1, wn1t, 512, 256);
    transpose_round<<<(256 * 256 + 255) / 256, 256>>>(Wn2, wn2t, 256, 256);
    round_h_kernel<<<(NN * 256 + 255) / 256, 256>>>(h);

    edge_kernel<<<NE / 128, 256, SMEM_BYTES>>>(coord, ei, be1, be2, bc1, Wc2);

    round_agg_kernel<<<(NN * 256 + 255) / 256, 256>>>();

    node_kernel<<<(NN + 127) / 128, 256, SMEM_BYTES>>>(h, bn1, bn2, out);
    coord_kernel<<<(NN + 255) / 256, 256>>>(coord, out);
}

// round 6
// speedup vs baseline: 1.2345x; 1.2345x over previous
#include <cuda_runtime.h>
#include <cstdint>
#include <cstddef>

#define NN 50000
#define NE 800000

// ---------------- scratch (no allocation allowed) ----------------
__device__ float g_agg[NN * 256];     // segment-sum of edge_feat
__device__ float g_cagg[NN * 4];      // {sum dx*phi, dy*phi, dz*phi, count}
__device__ float g_hr[NN * 256];      // tf32-rounded h
__device__ float g_P1[NN * 256];      // h @ We1[:, :256]^T
__device__ float g_P2[NN * 256];      // h @ We1[:, 256:512]^T
__device__ float g_We1at[256 * 256];  // [k][n] tf32, k = 0..255 of We1
__device__ float g_We1bt[256 * 256];  // [k][n] tf32, k = 256..511 of We1
__device__ float g_w512[256];         // We1[:, 512] (radial weight)
__device__ float g_We2t[256 * 256];   // [k][n]
__device__ float g_Wc1t[256 * 256];
__device__ float g_Wn1t[512 * 256];
__device__ float g_Wn2t[256 * 256];

// ---------------- edge kernel smem layout (bytes) ----------------
#define E_A2   0         // 128 x 260 floats = 133120
#define E_B    133120    // 2 x 16 x 264 floats = 33792
#define E_RS   166912    // 128 ints
#define E_CS   167424    // 128 ints
#define E_CD   167936    // 128 float4
#define E_PHI  169984    // 128 floats
#define E_BE1  170496    // 256 floats
#define E_BE2  171520
#define E_BC1  172544
#define E_W512 173568
#define E_WC2  174592
#define E_SMEM 175616

// ---------------- node / pre kernel smem layout ----------------
#define N_A1   0         // 2 x 128 x 20 floats = 20480
#define N_B    20480     // 2 x 16 x 264 floats = 33792
#define N_A2   54272     // 128 x 260 floats = 133120
#define N_IDX  187392    // 128 ints
#define N_B1   187904    // 256 floats
#define N_B2   188928    // 256 floats
#define N_SMEM 189952
#define P_SMEM 54784     // pre kernel: A1 + B + idx only

// ---------------- helpers ----------------
__device__ __forceinline__ uint32_t smem_u32(const void* p) {
    uint32_t a;
    asm("{ .reg .u64 t; cvta.to.shared.u64 t, %1; cvt.u32.u64 %0, t; }" : "=r"(a) : "l"(p));
    return a;
}
__device__ __forceinline__ void cpa16(uint32_t s, const void* g) {
    asm volatile("cp.async.cg.shared.global [%0], [%1], 16;" :: "r"(s), "l"(g));
}
__device__ __forceinline__ void cpcommit() { asm volatile("cp.async.commit_group;"); }
__device__ __forceinline__ void cpwait0() { asm volatile("cp.async.wait_group 0;"); }

__device__ __forceinline__ float to_tf32(float x) {
    uint32_t y;
    asm("cvt.rna.tf32.f32 %0, %1;" : "=r"(y) : "f"(x));
    return __uint_as_float(y);
}
__device__ __forceinline__ float silu_f(float x) { return x / (1.0f + __expf(-x)); }
__device__ __forceinline__ void red4(float* gp, float x, float y, float z, float w) {
    asm volatile("red.global.add.v4.f32 [%0], {%1,%2,%3,%4};"
                 :: "l"(gp), "f"(x), "f"(y), "f"(z), "f"(w) : "memory");
}

// One K=16 chunk of the warp-tiled GEMM. Warp tile 64x64, mma m16n8k8 tf32.
template <int SA>
__device__ __forceinline__ void gemm_chunk(const float* __restrict__ Ac,
                                           const float* __restrict__ Bc,
                                           float (&c)[4][8][4],
                                           int wm, int wn, int g, int t) {
#pragma unroll
    for (int k8 = 0; k8 < 16; k8 += 8) {
        uint32_t a[4][4];
#pragma unroll
        for (int i = 0; i < 4; i++) {
            const float* ap = Ac + (wm * 64 + i * 16 + g) * SA + k8 + t;
            a[i][0] = __float_as_uint(ap[0]);
            a[i][1] = __float_as_uint(ap[8 * SA]);
            a[i][2] = __float_as_uint(ap[4]);
            a[i][3] = __float_as_uint(ap[8 * SA + 4]);
        }
        uint32_t b[8][2];
#pragma unroll
        for (int j = 0; j < 8; j++) {
            const float* bp = Bc + (k8 + t) * 264 + wn * 64 + j * 8 + g;
            b[j][0] = __float_as_uint(bp[0]);
            b[j][1] = __float_as_uint(bp[4 * 264]);
        }
#pragma unroll
        for (int i = 0; i < 4; i++)
#pragma unroll
            for (int j = 0; j < 8; j++)
                asm volatile(
                    "mma.sync.aligned.m16n8k8.row.col.f32.tf32.tf32.f32 "
                    "{%0,%1,%2,%3},{%4,%5,%6,%7},{%8,%9},{%0,%1,%2,%3};"
                    : "+f"(c[i][j][0]), "+f"(c[i][j][1]), "+f"(c[i][j][2]), "+f"(c[i][j][3])
                    : "r"(a[i][0]), "r"(a[i][1]), "r"(a[i][2]), "r"(a[i][3]),
                      "r"(b[j][0]), "r"(b[j][1]));
    }
}

__device__ __forceinline__ void init_bias(float (&c)[4][8][4], const float* bs, int wn, int t) {
#pragma unroll
    for (int j = 0; j < 8; j++) {
        int col = wn * 64 + j * 8 + 2 * t;
        float b0 = bs[col], b1 = bs[col + 1];
#pragma unroll
        for (int i = 0; i < 4; i++) {
            c[i][j][0] = b0; c[i][j][1] = b1; c[i][j][2] = b0; c[i][j][3] = b1;
        }
    }
}

__device__ __forceinline__ void store_silu(const float (&c)[4][8][4], float* A2,
                                           int wm, int wn, int g, int t) {
#pragma unroll
    for (int i = 0; i < 4; i++) {
        int r0 = wm * 64 + i * 16 + g;
#pragma unroll
        for (int j = 0; j < 8; j++) {
            int col = wn * 64 + j * 8 + 2 * t;
            A2[r0 * 260 + col]           = to_tf32(silu_f(c[i][j][0]));
            A2[r0 * 260 + col + 1]       = to_tf32(silu_f(c[i][j][1]));
            A2[(r0 + 8) * 260 + col]     = to_tf32(silu_f(c[i][j][2]));
            A2[(r0 + 8) * 260 + col + 1] = to_tf32(silu_f(c[i][j][3]));
        }
    }
}

// ---------------- prep kernels ----------------
__global__ void round_h_kernel(const float* __restrict__ h) {
    int i = blockIdx.x * blockDim.x + threadIdx.x;
    if (i < NN * 256) g_hr[i] = to_tf32(h[i]);
}
__global__ void round_agg_kernel() {
    int i = blockIdx.x * blockDim.x + threadIdx.x;
    if (i < NN * 256) g_agg[i] = to_tf32(g_agg[i]);
}
__global__ void pack_we1(const float* __restrict__ We1) {
    int i = blockIdx.x * blockDim.x + threadIdx.x;
    if (i < 256 * 512) {
        int k = i >> 8, n = i & 255;
        float v = to_tf32(We1[n * 513 + k]);
        if (k < 256) g_We1at[k * 256 + n] = v;
        else         g_We1bt[(k - 256) * 256 + n] = v;
    }
    if (i < 256) g_w512[i] = to_tf32(We1[i * 513 + 512]);
}
__global__ void transpose_round(const float* __restrict__ W, float* __restrict__ Wt,
                                int K, int N) {
    int i = blockIdx.x * blockDim.x + threadIdx.x;
    if (i < K * N) {
        int k = i / N, n = i - k * N;
        Wt[i] = to_tf32(W[n * K + k]);
    }
}

// ---------------- precompute kernel: P = g_hr @ Wt (K=256, no bias) ----------------
__global__ __launch_bounds__(256, 1) void pre_kernel() {
    extern __shared__ char smem[];
    float* A1s = (float*)(smem + N_A1);
    float* Bsm = (float*)(smem + N_B);
    int* idx = (int*)(smem + P_SMEM - 512);

    const float* Wt = (blockIdx.y == 0) ? g_We1at : g_We1bt;
    float* P = (blockIdx.y == 0) ? g_P1 : g_P2;

    const int tid = threadIdx.x;
    const int warp = tid >> 5, lane = tid & 31;
    const int wm = warp >> 2, wn = warp & 3, g = lane >> 2, t = lane & 3;
    const int base = blockIdx.x * 128;
    const uint32_t sbase = smem_u32(smem);
    const uint32_t a1u = sbase + N_A1, bu = sbase + N_B;

    if (tid < 128) {
        int n = base + tid;
        idx[tid] = (n < NN) ? n : 0;
    }
    __syncthreads();

    float c[4][8][4];
#pragma unroll
    for (int i = 0; i < 4; i++)
#pragma unroll
        for (int j = 0; j < 8; j++) {
            c[i][j][0] = 0.f; c[i][j][1] = 0.f; c[i][j][2] = 0.f; c[i][j][3] = 0.f;
        }

    auto stageA = [&](int kc, int buf) {
        int k0 = kc * 16;
        int e = tid >> 1, half = tid & 1;
        const float* gp = g_hr + (size_t)idx[e] * 256 + k0 + half * 8;
        uint32_t d = a1u + (uint32_t)(buf * 2560 + e * 20 + half * 8) * 4u;
        cpa16(d, gp); cpa16(d + 16u, gp + 4);
    };
    auto stageB = [&](int kc, int buf) {
        int k0 = kc * 16;
#pragma unroll
        for (int it = 0; it < 4; it++) {
            int v = it * 256 + tid;
            int k = v >> 6, n = (v & 63) << 2;
            cpa16(bu + (uint32_t)(buf * 4224 + k * 264 + n) * 4u, Wt + (size_t)(k0 + k) * 256 + n);
        }
    };

    stageA(0, 0); stageB(0, 0); cpcommit();
    for (int kc = 0; kc < 16; kc++) {
        cpwait0();
        __syncthreads();
        if (kc + 1 < 16) { stageA(kc + 1, (kc + 1) & 1); stageB(kc + 1, (kc + 1) & 1); cpcommit(); }
        gemm_chunk<20>(A1s + (kc & 1) * 2560, Bsm + (kc & 1) * 4224, c, wm, wn, g, t);
    }

#pragma unroll
    for (int i = 0; i < 4; i++) {
        int r0 = wm * 64 + i * 16 + g;
        int n0 = base + r0, n1 = base + r0 + 8;
#pragma unroll
        for (int j = 0; j < 8; j++) {
            int col = wn * 64 + j * 8 + 2 * t;
            if (n0 < NN) {
                P[(size_t)n0 * 256 + col]     = c[i][j][0];
                P[(size_t)n0 * 256 + col + 1] = c[i][j][1];
            }
            if (n1 < NN) {
                P[(size_t)n1 * 256 + col]     = c[i][j][2];
                P[(size_t)n1 * 256 + col + 1] = c[i][j][3];
            }
        }
    }
}

// ---------------- edge kernel ----------------
__global__ __launch_bounds__(256, 1) void edge_kernel(
    const float* __restrict__ coordp, const int* __restrict__ ei,
    const float* __restrict__ be1, const float* __restrict__ be2,
    const float* __restrict__ bc1, const float* __restrict__ wc2) {
    extern __shared__ char smem[];
    float* A2  = (float*)(smem + E_A2);
    float* Bsm = (float*)(smem + E_B);
    int* rs = (int*)(smem + E_RS);
    int* cs = (int*)(smem + E_CS);
    float4* cd = (float4*)(smem + E_CD);
    float* phis = (float*)(smem + E_PHI);
    float* be1s = (float*)(smem + E_BE1);
    float* be2s = (float*)(smem + E_BE2);
    float* bc1s = (float*)(smem + E_BC1);
    float* w512s = (float*)(smem + E_W512);
    float* wc2s = (float*)(smem + E_WC2);

    const int tid = threadIdx.x;
    const int warp = tid >> 5, lane = tid & 31;
    const int wm = warp >> 2, wn = warp & 3, g = lane >> 2, t = lane & 3;
    const int ebase = blockIdx.x * 128;
    const uint32_t sbase = smem_u32(smem);
    const uint32_t bu = sbase + E_B;

    if (tid < 128) {
        int r = ei[ebase + tid], c = ei[NE + ebase + tid];
        rs[tid] = r; cs[tid] = c;
        float dx = coordp[r * 3 + 0] - coordp[c * 3 + 0];
        float dy = coordp[r * 3 + 1] - coordp[c * 3 + 1];
        float dz = coordp[r * 3 + 2] - coordp[c * 3 + 2];
        cd[tid] = make_float4(dx, dy, dz, dx * dx + dy * dy + dz * dz);
        phis[tid] = 0.f;
    }
    be1s[tid] = be1[tid]; be2s[tid] = be2[tid]; bc1s[tid] = bc1[tid];
    w512s[tid] = g_w512[tid];
    wc2s[tid] = to_tf32(wc2[tid]);
    __syncthreads();

    auto stageB = [&](const float* __restrict__ gW, int kc, int buf) {
        int k0 = kc * 16;
#pragma unroll
        for (int it = 0; it < 4; it++) {
            int v = it * 256 + tid;
            int k = v >> 6, n = (v & 63) << 2;
            cpa16(bu + (uint32_t)(buf * 4224 + k * 264 + n) * 4u, gW + (size_t)(k0 + k) * 256 + n);
        }
    };

    // stage first We2 chunk, then overlap prologue with it
    stageB(g_We2t, 0, 0); cpcommit();

    // prologue: A2 = tf32(silu(P1[row] + P2[col] + radial*w512 + be1))
#pragma unroll
    for (int it = 0; it < 32; it++) {
        int v = it * 256 + tid;
        int r = v >> 6, k4 = (v & 63) << 2;
        float4 a = *(const float4*)(g_P1 + (size_t)rs[r] * 256 + k4);
        float4 b = *(const float4*)(g_P2 + (size_t)cs[r] * 256 + k4);
        float4 w = *(const float4*)(w512s + k4);
        float4 bb = *(const float4*)(be1s + k4);
        float rad = cd[r].w;
        float4 o;
        o.x = to_tf32(silu_f(a.x + b.x + rad * w.x + bb.x));
        o.y = to_tf32(silu_f(a.y + b.y + rad * w.y + bb.y));
        o.z = to_tf32(silu_f(a.z + b.z + rad * w.z + bb.z));
        o.w = to_tf32(silu_f(a.w + b.w + rad * w.w + bb.w));
        *(float4*)(A2 + r * 260 + k4) = o;
    }

    float c[4][8][4];

    // ---- GEMM2: m @ We2^T (K=256) ----
    init_bias(c, be2s, wn, t);
    for (int kc = 0; kc < 16; kc++) {
        cpwait0();
        __syncthreads();
        if (kc + 1 < 16) { stageB(g_We2t, kc + 1, (kc + 1) & 1); cpcommit(); }
        gemm_chunk<260>(A2 + kc * 16, Bsm + (kc & 1) * 4224, c, wm, wn, g, t);
    }
    __syncthreads();
    store_silu(c, A2, wm, wn, g, t);   // A2 = edge_feat (tf32)
    stageB(g_Wc1t, 0, 0); cpcommit();

    // ---- GEMM3: edge_feat @ Wc1^T (K=256) ----
    init_bias(c, bc1s, wn, t);
    for (int kc = 0; kc < 16; kc++) {
        cpwait0();
        __syncthreads();
        if (kc + 1 < 16) { stageB(g_Wc1t, kc + 1, (kc + 1) & 1); cpcommit(); }
        gemm_chunk<260>(A2 + kc * 16, Bsm + (kc & 1) * 4224, c, wm, wn, g, t);
    }

    // phi_x[e] = silu(C3) . wc2
    {
        float pr[8];
#pragma unroll
        for (int k = 0; k < 8; k++) pr[k] = 0.f;
#pragma unroll
        for (int i = 0; i < 4; i++)
#pragma unroll
            for (int j = 0; j < 8; j++) {
                int col = wn * 64 + j * 8 + 2 * t;
                float w0 = wc2s[col], w1 = wc2s[col + 1];
                pr[i * 2]     += silu_f(c[i][j][0]) * w0 + silu_f(c[i][j][1]) * w1;
                pr[i * 2 + 1] += silu_f(c[i][j][2]) * w0 + silu_f(c[i][j][3]) * w1;
            }
#pragma unroll
        for (int k = 0; k < 8; k++) {
            pr[k] += __shfl_xor_sync(0xffffffffu, pr[k], 1);
            pr[k] += __shfl_xor_sync(0xffffffffu, pr[k], 2);
        }
        if (t == 0) {
#pragma unroll
            for (int i = 0; i < 4; i++) {
                atomicAdd(&phis[wm * 64 + i * 16 + g], pr[i * 2]);
                atomicAdd(&phis[wm * 64 + i * 16 + g + 8], pr[i * 2 + 1]);
            }
        }
    }
    __syncthreads();

    // coord aggregation
    if (tid < 128) {
        float4 d = cd[tid];
        float p = phis[tid];
        red4(&g_cagg[(size_t)rs[tid] * 4], d.x * p, d.y * p, d.z * p, 1.0f);
    }
    // feature aggregation from A2 (edge_feat)
#pragma unroll
    for (int it = 0; it < 32; it++) {
        int v = it * 256 + tid;
        int r = v >> 6, c4 = (v & 63) << 2;
        const float* sp = A2 + r * 260 + c4;
        red4(&g_agg[(size_t)rs[r] * 256 + c4], sp[0], sp[1], sp[2], sp[3]);
    }
}

// ---------------- node kernel ----------------
__global__ __launch_bounds__(256, 1) void node_kernel(
    const float* __restrict__ h, const float* __restrict__ bn1,
    const float* __restrict__ bn2, float* __restrict__ out) {
    extern __shared__ char smem[];
    float* A1s = (float*)(smem + N_A1);
    float* Bsm = (float*)(smem + N_B);
    float* A2  = (float*)(smem + N_A2);
    int* idx = (int*)(smem + N_IDX);
    float* b1s = (float*)(smem + N_B1);
    float* b2s = (float*)(smem + N_B2);

    const int tid = threadIdx.x;
    const int warp = tid >> 5, lane = tid & 31;
    const int wm = warp >> 2, wn = warp & 3, g = lane >> 2, t = lane & 3;
    const int base = blockIdx.x * 128;
    const uint32_t sbase = smem_u32(smem);
    const uint32_t a1u = sbase + N_A1, bu = sbase + N_B;

    if (tid < 128) {
        int n = base + tid;
        idx[tid] = (n < NN) ? n : 0;
    }
    b1s[tid] = bn1[tid]; b2s[tid] = bn2[tid];
    __syncthreads();

    float c[4][8][4];

    auto stageA = [&](int kc, int buf) {
        int k0 = kc * 16;
        const float* basep = (k0 < 256) ? g_hr : g_agg;
        int koff = k0 & 255;
        int e = tid >> 1, half = tid & 1;
        const float* gp = basep + (size_t)idx[e] * 256 + koff + half * 8;
        uint32_t d = a1u + (uint32_t)(buf * 2560 + e * 20 + half * 8) * 4u;
        cpa16(d, gp); cpa16(d + 16u, gp + 4);
    };
    auto stageB = [&](const float* __restrict__ gW, int kc, int buf) {
        int k0 = kc * 16;
#pragma unroll
        for (int it = 0; it < 4; it++) {
            int v = it * 256 + tid;
            int k = v >> 6, n = (v & 63) << 2;
            cpa16(bu + (uint32_t)(buf * 4224 + k * 264 + n) * 4u, gW + (size_t)(k0 + k) * 256 + n);
        }
    };

    // GEMM1: [h | agg] @ Wn1^T (K=512)
    init_bias(c, b1s, wn, t);
    stageA(0, 0); stageB(g_Wn1t, 0, 0); cpcommit();
    for (int kc = 0; kc < 32; kc++) {
        cpwait0();
        __syncthreads();
        if (kc + 1 < 32) { stageA(kc + 1, (kc + 1) & 1); stageB(g_Wn1t, kc + 1, (kc + 1) & 1); cpcommit(); }
        gemm_chunk<20>(A1s + (kc & 1) * 2560, Bsm + (kc & 1) * 4224, c, wm, wn, g, t);
    }
    __syncthreads();
    store_silu(c, A2, wm, wn, g, t);
    stageB(g_Wn2t, 0, 0); cpcommit();

    // GEMM2: @ Wn2^T (K=256), + bn2 + residual h
    init_bias(c, b2s, wn, t);
    for (int kc = 0; kc < 16; kc++) {
        cpwait0();
        __syncthreads();
        if (kc + 1 < 16) { stageB(g_Wn2t, kc + 1, (kc + 1) & 1); cpcommit(); }
        gemm_chunk<260>(A2 + kc * 16, Bsm + (kc & 1) * 4224, c, wm, wn, g, t);
    }
#pragma unroll
    for (int i = 0; i < 4; i++) {
        int r0 = wm * 64 + i * 16 + g;
        int n0 = base + r0, n1 = base + r0 + 8;
#pragma unroll
        for (int j = 0; j < 8; j++) {
            int col = wn * 64 + j * 8 + 2 * t;
            if (n0 < NN) {
                out[(size_t)n0 * 256 + col]     = c[i][j][0] + h[(size_t)n0 * 256 + col];
                out[(size_t)n0 * 256 + col + 1] = c[i][j][1] + h[(size_t)n0 * 256 + col + 1];
            }
            if (n1 < NN) {
                out[(size_t)n1 * 256 + col]     = c[i][j][2] + h[(size_t)n1 * 256 + col];
                out[(size_t)n1 * 256 + col + 1] = c[i][j][3] + h[(size_t)n1 * 256 + col + 1];
            }
        }
    }
}

// ---------------- coord finish ----------------
__global__ void coord_kernel(const float* __restrict__ coordp, float* __restrict__ out) {
    int n = blockIdx.x * blockDim.x + threadIdx.x;
    if (n < NN) {
        float cnt = g_cagg[n * 4 + 3];
        float s = 1.0f / fmaxf(cnt, 1.0f);
        float* o = out + (size_t)NN * 256 + (size_t)n * 3;
        o[0] = coordp[n * 3 + 0] + g_cagg[n * 4 + 0] * s;
        o[1] = coordp[n * 3 + 1] + g_cagg[n * 4 + 1] * s;
        o[2] = coordp[n * 3 + 2] + g_cagg[n * 4 + 2] * s;
    }
}

// ---------------- host ----------------
extern "C" void kernel_launch(void* const* d_in, const int* in_sizes, int n_in,
                              void* d_out, int out_size) {
    (void)in_sizes; (void)n_in; (void)out_size;
    const float* h     = (const float*)d_in[0];
    const int*   ei    = (const int*)d_in[1];
    const float* coord = (const float*)d_in[2];
    const float* We1   = (const float*)d_in[3];
    const float* be1   = (const float*)d_in[4];
    const float* We2   = (const float*)d_in[5];
    const float* be2   = (const float*)d_in[6];
    const float* Wn1   = (const float*)d_in[7];
    const float* bn1   = (const float*)d_in[8];
    const float* Wn2   = (const float*)d_in[9];
    const float* bn2   = (const float*)d_in[10];
    const float* Wc1   = (const float*)d_in[11];
    const float* bc1   = (const float*)d_in[12];
    const float* Wc2   = (const float*)d_in[13];
    float* out = (float*)d_out;

    cudaFuncSetAttribute(edge_kernel, cudaFuncAttributeMaxDynamicSharedMemorySize, E_SMEM);
    cudaFuncSetAttribute(node_kernel, cudaFuncAttributeMaxDynamicSharedMemorySize, N_SMEM);
    cudaFuncSetAttribute(pre_kernel,  cudaFuncAttributeMaxDynamicSharedMemorySize, P_SMEM);

    void* agg_p = nullptr; void* cagg_p = nullptr;
    cudaGetSymbolAddress(&agg_p, g_agg);
    cudaGetSymbolAddress(&cagg_p, g_cagg);
    cudaMemsetAsync(agg_p, 0, sizeof(float) * (size_t)NN * 256, 0);
    cudaMemsetAsync(cagg_p, 0, sizeof(float) * (size_t)NN * 4, 0);

    float* we2t; float* wc1t; float* wn1t; float* wn2t;
    cudaGetSymbolAddress((void**)&we2t, g_We2t);
    cudaGetSymbolAddress((void**)&wc1t, g_Wc1t);
    cudaGetSymbolAddress((void**)&wn1t, g_Wn1t);
    cudaGetSymbolAddress((void**)&wn2t, g_Wn2t);

    pack_we1<<<(256 * 512 + 255) / 256, 256>>>(We1);
    transpose_round<<<(256 * 256 + 255) / 256, 256>>>(We2, we2t, 256, 256);
    transpose_round<<<(256 * 256 + 255) / 256, 256>>>(Wc1, wc1t, 256, 256);
    transpose_round<<<(512 * 256 + 255) / 256, 256>>>(Wn1, wn1t, 512, 256);
    transpose_round<<<(256 * 256 + 255) / 256, 256>>>(Wn2, wn2t, 256, 256);
    round_h_kernel<<<(NN * 256 + 255) / 256, 256>>>(h);

    pre_kernel<<<dim3((NN + 127) / 128, 2), 256, P_SMEM>>>();

    edge_kernel<<<NE / 128, 256, E_SMEM>>>(coord, ei, be1, be2, bc1, Wc2);

    round_agg_kernel<<<(NN * 256 + 255) / 256, 256>>>();

    node_kernel<<<(NN + 127) / 128, 256, N_SMEM>>>(h, bn1, bn2, out);
    coord_kernel<<<(NN + 255) / 256, 256>>>(coord, out);
}

// round 7
// speedup vs baseline: 1.5254x; 1.2356x over previous
#include <cuda_runtime.h>
#include <cuda_fp16.h>
#include <cstdint>
#include <cstddef>

#define NN 50000
#define NE 800000

// ---------------- scratch (no allocation allowed) ----------------
__device__ float  g_agg[NN * 256];     // fp32 segment-sum of edge_feat
__device__ __half g_aggh[NN * 256];    // half copy for node GEMM1
__device__ float  g_cagg[NN * 4];      // {sum dx*phi, dy*phi, dz*phi, count}
__device__ __half g_hh[NN * 256];      // half-rounded h
__device__ float  g_P1[NN * 256];      // h @ We1[:, :256]^T   (fp32)
__device__ float  g_P2[NN * 256];      // h @ We1[:, 256:512]^T (fp32)
__device__ __half g_We1ah[256 * 256];  // [n][k] half, k = 0..255
__device__ __half g_We1bh[256 * 256];  // [n][k] half, k = 256..511
__device__ float  g_w512[256];         // We1[:, 512] (radial weight, fp32)
__device__ __half g_We2h[256 * 256];   // [n][k] half
__device__ __half g_Wc1h[256 * 256];
__device__ __half g_Wn1h[256 * 512];
__device__ __half g_Wn2h[256 * 256];

// ---------------- edge kernel smem (bytes) ----------------
#define E_A2   0         // 128 x 264 halves = 67584
#define E_B    67584     // 2 x 256 x 40 halves = 40960
#define E_RS   108544    // 128 ints
#define E_CS   109056
#define E_CD   109568    // 128 float4
#define E_PHI  111616    // 128 floats
#define E_BE1  112128    // 256 floats
#define E_W512 113152
#define E_BE2  114176
#define E_BC1  115200
#define E_WC2  116224
#define E_SMEM 117248

// ---------------- node / pre kernel smem ----------------
#define N_A1   0         // 2 x 128 x 40 halves = 20480
#define N_B    20480     // 2 x 256 x 40 halves = 40960
#define N_A2   61440     // 128 x 264 halves = 67584
#define N_IDX  129024    // 128 ints
#define N_B1   129536    // 256 floats
#define N_B2   130560    // 256 floats
#define N_SMEM 131584
#define P_IDX  61440
#define P_SMEM 61952

// ---------------- helpers ----------------
__device__ __forceinline__ uint32_t smem_u32(const void* p) {
    uint32_t a;
    asm("{ .reg .u64 t; cvta.to.shared.u64 t, %1; cvt.u32.u64 %0, t; }" : "=r"(a) : "l"(p));
    return a;
}
__device__ __forceinline__ void cpa16(uint32_t s, const void* g) {
    asm volatile("cp.async.cg.shared.global [%0], [%1], 16;" :: "r"(s), "l"(g));
}
__device__ __forceinline__ void cpcommit() { asm volatile("cp.async.commit_group;"); }
__device__ __forceinline__ void cpwait0() { asm volatile("cp.async.wait_group 0;"); }

__device__ __forceinline__ float silu_f(float x) { return x / (1.0f + __expf(-x)); }
__device__ __forceinline__ void red4(float* gp, float x, float y, float z, float w) {
    asm volatile("red.global.add.v4.f32 [%0], {%1,%2,%3,%4};"
                 :: "l"(gp), "f"(x), "f"(y), "f"(z), "f"(w) : "memory");
}

// One K=32 chunk, warp tile 64x64, mma m16n8k16 f16 (fp32 accum).
// A: halves, row stride SA (264 resident / 40 chunk-tile). B: halves, [n][40].
template <int SA>
__device__ __forceinline__ void gemm_chunk_h(const __half* __restrict__ Ac,
                                             const __half* __restrict__ Bc,
                                             float (&c)[4][8][4],
                                             int wm, int wn, int g, int t) {
#pragma unroll
    for (int s = 0; s < 2; s++) {
        int kb = s * 16 + 2 * t;
        uint32_t a[4][4];
#pragma unroll
        for (int i = 0; i < 4; i++) {
            const __half* ap = Ac + (wm * 64 + i * 16 + g) * SA + kb;
            a[i][0] = *(const uint32_t*)(ap);
            a[i][1] = *(const uint32_t*)(ap + 8 * SA);
            a[i][2] = *(const uint32_t*)(ap + 8);
            a[i][3] = *(const uint32_t*)(ap + 8 * SA + 8);
        }
        uint32_t b[8][2];
#pragma unroll
        for (int j = 0; j < 8; j++) {
            const __half* bp = Bc + (wn * 64 + j * 8 + g) * 40 + kb;
            b[j][0] = *(const uint32_t*)(bp);
            b[j][1] = *(const uint32_t*)(bp + 8);
        }
#pragma unroll
        for (int i = 0; i < 4; i++)
#pragma unroll
            for (int j = 0; j < 8; j++)
                asm volatile(
                    "mma.sync.aligned.m16n8k16.row.col.f32.f16.f16.f32 "
                    "{%0,%1,%2,%3},{%4,%5,%6,%7},{%8,%9},{%0,%1,%2,%3};"
                    : "+f"(c[i][j][0]), "+f"(c[i][j][1]), "+f"(c[i][j][2]), "+f"(c[i][j][3])
                    : "r"(a[i][0]), "r"(a[i][1]), "r"(a[i][2]), "r"(a[i][3]),
                      "r"(b[j][0]), "r"(b[j][1]));
    }
}

__device__ __forceinline__ void init_bias(float (&c)[4][8][4], const float* bs, int wn, int t) {
#pragma unroll
    for (int j = 0; j < 8; j++) {
        int col = wn * 64 + j * 8 + 2 * t;
        float b0 = bs[col], b1 = bs[col + 1];
#pragma unroll
        for (int i = 0; i < 4; i++) {
            c[i][j][0] = b0; c[i][j][1] = b1; c[i][j][2] = b0; c[i][j][3] = b1;
        }
    }
}

// Apply SiLU, round to half, write to A2 (stride 264 halves).
__device__ __forceinline__ void store_silu_h(const float (&c)[4][8][4], __half* A2,
                                             int wm, int wn, int g, int t) {
#pragma unroll
    for (int i = 0; i < 4; i++) {
        int r0 = wm * 64 + i * 16 + g;
#pragma unroll
        for (int j = 0; j < 8; j++) {
            int col = wn * 64 + j * 8 + 2 * t;
            *(__half2*)(A2 + r0 * 264 + col) =
                __floats2half2_rn(silu_f(c[i][j][0]), silu_f(c[i][j][1]));
            *(__half2*)(A2 + (r0 + 8) * 264 + col) =
                __floats2half2_rn(silu_f(c[i][j][2]), silu_f(c[i][j][3]));
        }
    }
}

// ---------------- prep kernels ----------------
__global__ void round_h_kernel(const float* __restrict__ h) {
    int i = blockIdx.x * blockDim.x + threadIdx.x;
    if (i < NN * 256) g_hh[i] = __float2half_rn(h[i]);
}
__global__ void round_agg_kernel() {
    int i = blockIdx.x * blockDim.x + threadIdx.x;
    if (i < NN * 256) g_aggh[i] = __float2half_rn(g_agg[i]);
}
__global__ void pack_we1(const float* __restrict__ We1) {
    int i = blockIdx.x * blockDim.x + threadIdx.x;
    if (i < 256 * 512) {
        int n = i >> 9, k = i & 511;
        __half v = __float2half_rn(We1[n * 513 + k]);
        if (k < 256) g_We1ah[n * 256 + k] = v;
        else         g_We1bh[n * 256 + (k - 256)] = v;
    }
    if (i < 256) g_w512[i] = We1[i * 513 + 512];
}
__global__ void pack_half(const float* __restrict__ W, __half* __restrict__ Wh, int count) {
    int i = blockIdx.x * blockDim.x + threadIdx.x;
    if (i < count) Wh[i] = __float2half_rn(W[i]);
}

// ---------------- precompute kernel: P = h @ We1{a,b}^T (K=256, fp32 out) ----------------
__global__ __launch_bounds__(256, 1) void pre_kernel() {
    extern __shared__ char smem[];
    __half* A1s = (__half*)(smem + N_A1);
    __half* Bsm = (__half*)(smem + N_B);
    int* idx = (int*)(smem + P_IDX);

    const __half* Wh = (blockIdx.y == 0) ? g_We1ah : g_We1bh;
    float* P = (blockIdx.y == 0) ? g_P1 : g_P2;

    const int tid = threadIdx.x;
    const int warp = tid >> 5, lane = tid & 31;
    const int wm = warp >> 2, wn = warp & 3, g = lane >> 2, t = lane & 3;
    const int base = blockIdx.x * 128;
    const uint32_t sbase = smem_u32(smem);
    const uint32_t a1u = sbase + N_A1, bu = sbase + N_B;

    if (tid < 128) {
        int n = base + tid;
        idx[tid] = (n < NN) ? n : 0;
    }
    __syncthreads();

    float c[4][8][4];
#pragma unroll
    for (int i = 0; i < 4; i++)
#pragma unroll
        for (int j = 0; j < 8; j++) {
            c[i][j][0] = 0.f; c[i][j][1] = 0.f; c[i][j][2] = 0.f; c[i][j][3] = 0.f;
        }

    auto stageA = [&](int kc, int buf) {
#pragma unroll
        for (int it = 0; it < 2; it++) {
            int v = it * 256 + tid;
            int r = v >> 2, seg = v & 3;
            cpa16(a1u + (uint32_t)(buf * 10240 + r * 80 + seg * 16),
                  g_hh + (size_t)idx[r] * 256 + kc * 32 + seg * 8);
        }
    };
    auto stageB = [&](int kc, int buf) {
#pragma unroll
        for (int it = 0; it < 4; it++) {
            int v = it * 256 + tid;
            int n = v >> 2, seg = v & 3;
            cpa16(bu + (uint32_t)(buf * 20480 + n * 80 + seg * 16),
                  Wh + (size_t)n * 256 + kc * 32 + seg * 8);
        }
    };

    stageA(0, 0); stageB(0, 0); cpcommit();
    for (int kc = 0; kc < 8; kc++) {
        cpwait0();
        __syncthreads();
        if (kc + 1 < 8) { stageA(kc + 1, (kc + 1) & 1); stageB(kc + 1, (kc + 1) & 1); cpcommit(); }
        gemm_chunk_h<40>(A1s + (kc & 1) * 5120, Bsm + (kc & 1) * 10240, c, wm, wn, g, t);
    }

#pragma unroll
    for (int i = 0; i < 4; i++) {
        int r0 = wm * 64 + i * 16 + g;
        int n0 = base + r0, n1 = base + r0 + 8;
#pragma unroll
        for (int j = 0; j < 8; j++) {
            int col = wn * 64 + j * 8 + 2 * t;
            if (n0 < NN) {
                P[(size_t)n0 * 256 + col]     = c[i][j][0];
                P[(size_t)n0 * 256 + col + 1] = c[i][j][1];
            }
            if (n1 < NN) {
                P[(size_t)n1 * 256 + col]     = c[i][j][2];
                P[(size_t)n1 * 256 + col + 1] = c[i][j][3];
            }
        }
    }
}

// ---------------- edge kernel ----------------
__global__ __launch_bounds__(256, 1) void edge_kernel(
    const float* __restrict__ coordp, const int* __restrict__ ei,
    const float* __restrict__ be1, const float* __restrict__ be2,
    const float* __restrict__ bc1, const float* __restrict__ wc2) {
    extern __shared__ char smem[];
    __half* A2  = (__half*)(smem + E_A2);
    __half* Bsm = (__half*)(smem + E_B);
    int* rs = (int*)(smem + E_RS);
    int* cs = (int*)(smem + E_CS);
    float4* cd = (float4*)(smem + E_CD);
    float* phis = (float*)(smem + E_PHI);
    float* be1s = (float*)(smem + E_BE1);
    float* w512s = (float*)(smem + E_W512);
    float* be2s = (float*)(smem + E_BE2);
    float* bc1s = (float*)(smem + E_BC1);
    float* wc2s = (float*)(smem + E_WC2);

    const int tid = threadIdx.x;
    const int warp = tid >> 5, lane = tid & 31;
    const int wm = warp >> 2, wn = warp & 3, g = lane >> 2, t = lane & 3;
    const int ebase = blockIdx.x * 128;
    const uint32_t sbase = smem_u32(smem);
    const uint32_t bu = sbase + E_B;

    if (tid < 128) {
        int r = ei[ebase + tid], c = ei[NE + ebase + tid];
        rs[tid] = r; cs[tid] = c;
        float dx = coordp[r * 3 + 0] - coordp[c * 3 + 0];
        float dy = coordp[r * 3 + 1] - coordp[c * 3 + 1];
        float dz = coordp[r * 3 + 2] - coordp[c * 3 + 2];
        cd[tid] = make_float4(dx, dy, dz, dx * dx + dy * dy + dz * dz);
        phis[tid] = 0.f;
    }
    be1s[tid] = be1[tid]; w512s[tid] = g_w512[tid];
    be2s[tid] = be2[tid]; bc1s[tid] = bc1[tid]; wc2s[tid] = wc2[tid];
    __syncthreads();

    auto stageB = [&](const __half* __restrict__ Wh, int kc, int buf) {
#pragma unroll
        for (int it = 0; it < 4; it++) {
            int v = it * 256 + tid;
            int n = v >> 2, seg = v & 3;
            cpa16(bu + (uint32_t)(buf * 20480 + n * 80 + seg * 16),
                  Wh + (size_t)n * 256 + kc * 32 + seg * 8);
        }
    };

    // stage first We2 chunk, then overlap prologue with it
    stageB(g_We2h, 0, 0); cpcommit();

    // prologue: A2 = half(silu(P1[row] + P2[col] + radial*w512 + be1))
#pragma unroll
    for (int it = 0; it < 32; it++) {
        int v = it * 256 + tid;
        int r = v >> 6, k4 = (v & 63) << 2;
        float4 a = *(const float4*)(g_P1 + (size_t)rs[r] * 256 + k4);
        float4 b = *(const float4*)(g_P2 + (size_t)cs[r] * 256 + k4);
        float4 w = *(const float4*)(w512s + k4);
        float4 bb = *(const float4*)(be1s + k4);
        float rad = cd[r].w;
        __half2 lo = __floats2half2_rn(silu_f(a.x + b.x + rad * w.x + bb.x),
                                       silu_f(a.y + b.y + rad * w.y + bb.y));
        __half2 hi = __floats2half2_rn(silu_f(a.z + b.z + rad * w.z + bb.z),
                                       silu_f(a.w + b.w + rad * w.w + bb.w));
        *(__half2*)(A2 + r * 264 + k4) = lo;
        *(__half2*)(A2 + r * 264 + k4 + 2) = hi;
    }

    float c[4][8][4];

    // ---- GEMM2: m @ We2^T (K=256, 8 chunks) ----
    init_bias(c, be2s, wn, t);
    for (int kc = 0; kc < 8; kc++) {
        cpwait0();
        __syncthreads();
        if (kc + 1 < 8) { stageB(g_We2h, kc + 1, (kc + 1) & 1); cpcommit(); }
        gemm_chunk_h<264>(A2 + kc * 32, Bsm + (kc & 1) * 10240, c, wm, wn, g, t);
    }
    __syncthreads();
    store_silu_h(c, A2, wm, wn, g, t);   // A2 = edge_feat (half)
    stageB(g_Wc1h, 0, 0); cpcommit();

    // ---- GEMM3: edge_feat @ Wc1^T (K=256, 8 chunks) ----
    init_bias(c, bc1s, wn, t);
    for (int kc = 0; kc < 8; kc++) {
        cpwait0();
        __syncthreads();
        if (kc + 1 < 8) { stageB(g_Wc1h, kc + 1, (kc + 1) & 1); cpcommit(); }
        gemm_chunk_h<264>(A2 + kc * 32, Bsm + (kc & 1) * 10240, c, wm, wn, g, t);
    }

    // phi_x[e] = silu(C3) . wc2  (fp32)
    {
        float pr[8];
#pragma unroll
        for (int k = 0; k < 8; k++) pr[k] = 0.f;
#pragma unroll
        for (int i = 0; i < 4; i++)
#pragma unroll
            for (int j = 0; j < 8; j++) {
                int col = wn * 64 + j * 8 + 2 * t;
                float w0 = wc2s[col], w1 = wc2s[col + 1];
                pr[i * 2]     += silu_f(c[i][j][0]) * w0 + silu_f(c[i][j][1]) * w1;
                pr[i * 2 + 1] += silu_f(c[i][j][2]) * w0 + silu_f(c[i][j][3]) * w1;
            }
#pragma unroll
        for (int k = 0; k < 8; k++) {
            pr[k] += __shfl_xor_sync(0xffffffffu, pr[k], 1);
            pr[k] += __shfl_xor_sync(0xffffffffu, pr[k], 2);
        }
        if (t == 0) {
#pragma unroll
            for (int i = 0; i < 4; i++) {
                atomicAdd(&phis[wm * 64 + i * 16 + g], pr[i * 2]);
                atomicAdd(&phis[wm * 64 + i * 16 + g + 8], pr[i * 2 + 1]);
            }
        }
    }
    __syncthreads();

    // coord aggregation
    if (tid < 128) {
        float4 d = cd[tid];
        float p = phis[tid];
        red4(&g_cagg[(size_t)rs[tid] * 4], d.x * p, d.y * p, d.z * p, 1.0f);
    }
    // feature aggregation: edge_feat (half) -> fp32 red4
#pragma unroll
    for (int it = 0; it < 32; it++) {
        int v = it * 256 + tid;
        int r = v >> 6, c4 = (v & 63) << 2;
        __half2 p0 = *(const __half2*)(A2 + r * 264 + c4);
        __half2 p1 = *(const __half2*)(A2 + r * 264 + c4 + 2);
        red4(&g_agg[(size_t)rs[r] * 256 + c4],
             __low2float(p0), __high2float(p0), __low2float(p1), __high2float(p1));
    }
}

// ---------------- node kernel ----------------
__global__ __launch_bounds__(256, 1) void node_kernel(
    const float* __restrict__ h, const float* __restrict__ bn1,
    const float* __restrict__ bn2, float* __restrict__ out) {
    extern __shared__ char smem[];
    __half* A1s = (__half*)(smem + N_A1);
    __half* Bsm = (__half*)(smem + N_B);
    __half* A2  = (__half*)(smem + N_A2);
    int* idx = (int*)(smem + N_IDX);
    float* b1s = (float*)(smem + N_B1);
    float* b2s = (float*)(smem + N_B2);

    const int tid = threadIdx.x;
    const int warp = tid >> 5, lane = tid & 31;
    const int wm = warp >> 2, wn = warp & 3, g = lane >> 2, t = lane & 3;
    const int base = blockIdx.x * 128;
    const uint32_t sbase = smem_u32(smem);
    const uint32_t a1u = sbase + N_A1, bu = sbase + N_B;

    if (tid < 128) {
        int n = base + tid;
        idx[tid] = (n < NN) ? n : 0;
    }
    b1s[tid] = bn1[tid]; b2s[tid] = bn2[tid];
    __syncthreads();

    float c[4][8][4];

    auto stageA = [&](int kc, int buf) {
        const __half* basep = (kc < 8) ? g_hh : g_aggh;
        int koff = (kc & 7) * 32;
#pragma unroll
        for (int it = 0; it < 2; it++) {
            int v = it * 256 + tid;
            int r = v >> 2, seg = v & 3;
            cpa16(a1u + (uint32_t)(buf * 10240 + r * 80 + seg * 16),
                  basep + (size_t)idx[r] * 256 + koff + seg * 8);
        }
    };
    auto stageB = [&](const __half* __restrict__ Wh, int kstride, int kc, int buf) {
#pragma unroll
        for (int it = 0; it < 4; it++) {
            int v = it * 256 + tid;
            int n = v >> 2, seg = v & 3;
            cpa16(bu + (uint32_t)(buf * 20480 + n * 80 + seg * 16),
                  Wh + (size_t)n * kstride + kc * 32 + seg * 8);
        }
    };

    // GEMM1: [h | agg] @ Wn1^T (K=512, 16 chunks)
    init_bias(c, b1s, wn, t);
    stageA(0, 0); stageB(g_Wn1h, 512, 0, 0); cpcommit();
    for (int kc = 0; kc < 16; kc++) {
        cpwait0();
        __syncthreads();
        if (kc + 1 < 16) { stageA(kc + 1, (kc + 1) & 1); stageB(g_Wn1h, 512, kc + 1, (kc + 1) & 1); cpcommit(); }
        gemm_chunk_h<40>(A1s + (kc & 1) * 5120, Bsm + (kc & 1) * 10240, c, wm, wn, g, t);
    }
    __syncthreads();
    store_silu_h(c, A2, wm, wn, g, t);
    stageB(g_Wn2h, 256, 0, 0); cpcommit();

    // GEMM2: @ Wn2^T (K=256, 8 chunks), + bn2 + residual h
    init_bias(c, b2s, wn, t);
    for (int kc = 0; kc < 8; kc++) {
        cpwait0();
        __syncthreads();
        if (kc + 1 < 8) { stageB(g_Wn2h, 256, kc + 1, (kc + 1) & 1); cpcommit(); }
        gemm_chunk_h<264>(A2 + kc * 32, Bsm + (kc & 1) * 10240, c, wm, wn, g, t);
    }
#pragma unroll
    for (int i = 0; i < 4; i++) {
        int r0 = wm * 64 + i * 16 + g;
        int n0 = base + r0, n1 = base + r0 + 8;
#pragma unroll
        for (int j = 0; j < 8; j++) {
            int col = wn * 64 + j * 8 + 2 * t;
            if (n0 < NN) {
                out[(size_t)n0 * 256 + col]     = c[i][j][0] + h[(size_t)n0 * 256 + col];
                out[(size_t)n0 * 256 + col + 1] = c[i][j][1] + h[(size_t)n0 * 256 + col + 1];
            }
            if (n1 < NN) {
                out[(size_t)n1 * 256 + col]     = c[i][j][2] + h[(size_t)n1 * 256 + col];
                out[(size_t)n1 * 256 + col + 1] = c[i][j][3] + h[(size_t)n1 * 256 + col + 1];
            }
        }
    }
}

// ---------------- coord finish ----------------
__global__ void coord_kernel(const float* __restrict__ coordp, float* __restrict__ out) {
    int n = blockIdx.x * blockDim.x + threadIdx.x;
    if (n < NN) {
        float cnt = g_cagg[n * 4 + 3];
        float s = 1.0f / fmaxf(cnt, 1.0f);
        float* o = out + (size_t)NN * 256 + (size_t)n * 3;
        o[0] = coordp[n * 3 + 0] + g_cagg[n * 4 + 0] * s;
        o[1] = coordp[n * 3 + 1] + g_cagg[n * 4 + 1] * s;
        o[2] = coordp[n * 3 + 2] + g_cagg[n * 4 + 2] * s;
    }
}

// ---------------- host ----------------
extern "C" void kernel_launch(void* const* d_in, const int* in_sizes, int n_in,
                              void* d_out, int out_size) {
    (void)in_sizes; (void)n_in; (void)out_size;
    const float* h     = (const float*)d_in[0];
    const int*   ei    = (const int*)d_in[1];
    const float* coord = (const float*)d_in[2];
    const float* We1   = (const float*)d_in[3];
    const float* be1   = (const float*)d_in[4];
    const float* We2   = (const float*)d_in[5];
    const float* be2   = (const float*)d_in[6];
    const float* Wn1   = (const float*)d_in[7];
    const float* bn1   = (const float*)d_in[8];
    const float* Wn2   = (const float*)d_in[9];
    const float* bn2   = (const float*)d_in[10];
    const float* Wc1   = (const float*)d_in[11];
    const float* bc1   = (const float*)d_in[12];
    const float* Wc2   = (const float*)d_in[13];
    float* out = (float*)d_out;

    cudaFuncSetAttribute(edge_kernel, cudaFuncAttributeMaxDynamicSharedMemorySize, E_SMEM);
    cudaFuncSetAttribute(node_kernel, cudaFuncAttributeMaxDynamicSharedMemorySize, N_SMEM);
    cudaFuncSetAttribute(pre_kernel,  cudaFuncAttributeMaxDynamicSharedMemorySize, P_SMEM);

    void* agg_p = nullptr; void* cagg_p = nullptr;
    cudaGetSymbolAddress(&agg_p, g_agg);
    cudaGetSymbolAddress(&cagg_p, g_cagg);
    cudaMemsetAsync(agg_p, 0, sizeof(float) * (size_t)NN * 256, 0);
    cudaMemsetAsync(cagg_p, 0, sizeof(float) * (size_t)NN * 4, 0);

    __half* we2h; __half* wc1h; __half* wn1h; __half* wn2h;
    cudaGetSymbolAddress((void**)&we2h, g_We2h);
    cudaGetSymbolAddress((void**)&wc1h, g_Wc1h);
    cudaGetSymbolAddress((void**)&wn1h, g_Wn1h);
    cudaGetSymbolAddress((void**)&wn2h, g_Wn2h);

    pack_we1<<<(256 * 512 + 255) / 256, 256>>>(We1);
    pack_half<<<(256 * 256 + 255) / 256, 256>>>(We2, we2h, 256 * 256);
    pack_half<<<(256 * 256 + 255) / 256, 256>>>(Wc1, wc1h, 256 * 256);
    pack_half<<<(256 * 512 + 255) / 256, 256>>>(Wn1, wn1h, 256 * 512);
    pack_half<<<(256 * 256 + 255) / 256, 256>>>(Wn2, wn2h, 256 * 256);
    round_h_kernel<<<(NN * 256 + 255) / 256, 256>>>(h);

    pre_kernel<<<dim3((NN + 127) / 128, 2), 256, P_SMEM>>>();

    edge_kernel<<<NE / 128, 256, E_SMEM>>>(coord, ei, be1, be2, bc1, Wc2);

    round_agg_kernel<<<(NN * 256 + 255) / 256, 256>>>();

    node_kernel<<<(NN + 127) / 128, 256, N_SMEM>>>(h, bn1, bn2, out);
    coord_kernel<<<(NN + 255) / 256, 256>>>(coord, out);
}

// round 8
// speedup vs baseline: 2.0819x; 1.3649x over previous
#include <cuda_runtime.h>
#include <cuda_fp16.h>
#include <cstdint>
#include <cstddef>

#define NN 50000
#define NE 800000

// ---------------- scratch (no allocation allowed) ----------------
__device__ float  g_agg[NN * 256];     // fp32 segment-sum of edge_feat
__device__ __half g_aggh[NN * 256];    // half copy for node GEMM1
__device__ float  g_cagg[NN * 4];      // {sum dx*phi, dy*phi, dz*phi, count}
__device__ __half g_hh[NN * 256];      // half-rounded h
__device__ float  g_P1[NN * 256];      // h @ We1[:, :256]^T   (fp32)
__device__ float  g_P2[NN * 256];      // h @ We1[:, 256:512]^T (fp32)
__device__ __half g_We1ah[256 * 256];  // [n][k] half, k = 0..255
__device__ __half g_We1bh[256 * 256];  // [n][k] half, k = 256..511
__device__ float  g_w512[256];         // We1[:, 512] (radial weight, fp32)
__device__ __half g_We2h[256 * 256];   // [n][k] half
__device__ __half g_Wc1h[256 * 256];
__device__ __half g_Wn1h[256 * 512];
__device__ __half g_Wn2h[256 * 256];

// ---------------- edge kernel smem (bytes) ----------------
#define E_A2   0         // 128 x 264 halves = 67584
#define E_B    67584     // 2 x 256 x 72 halves = 73728
#define E_RS   141312    // 128 ints
#define E_CS   141824
#define E_CD   142336    // 128 float4
#define E_PHI  144384    // 128 floats
#define E_BE1  144896    // 256 floats
#define E_W512 145920
#define E_BE2  146944
#define E_BC1  147968
#define E_WC2  148992
#define E_SMEM 150016

// ---------------- node / pre kernel smem ----------------
#define N_A1   0         // 2 x 128 x 40 halves = 20480
#define N_B    20480     // 2 x 256 x 40 halves = 40960
#define N_A2   61440     // 128 x 264 halves = 67584
#define N_IDX  129024    // 128 ints
#define N_B1   129536    // 256 floats
#define N_B2   130560    // 256 floats
#define N_SMEM 131584
#define P_IDX  61440
#define P_SMEM 61952

// ---------------- helpers ----------------
__device__ __forceinline__ uint32_t smem_u32(const void* p) {
    uint32_t a;
    asm("{ .reg .u64 t; cvta.to.shared.u64 t, %1; cvt.u32.u64 %0, t; }" : "=r"(a) : "l"(p));
    return a;
}
__device__ __forceinline__ void cpa16(uint32_t s, const void* g) {
    asm volatile("cp.async.cg.shared.global [%0], [%1], 16;" :: "r"(s), "l"(g));
}
__device__ __forceinline__ void cpcommit() { asm volatile("cp.async.commit_group;"); }
__device__ __forceinline__ void cpwait0() { asm volatile("cp.async.wait_group 0;"); }

__device__ __forceinline__ float silu_f(float x) { return x / (1.0f + __expf(-x)); }
__device__ __forceinline__ void red4(float* gp, float x, float y, float z, float w) {
    asm volatile("red.global.add.v4.f32 [%0], {%1,%2,%3,%4};"
                 :: "l"(gp), "f"(x), "f"(y), "f"(z), "f"(w) : "memory");
}

#define MMA_H(c, a, b) \
    asm volatile( \
        "mma.sync.aligned.m16n8k16.row.col.f32.f16.f16.f32 " \
        "{%0,%1,%2,%3},{%4,%5,%6,%7},{%8,%9},{%0,%1,%2,%3};" \
        : "+f"((c)[0]), "+f"((c)[1]), "+f"((c)[2]), "+f"((c)[3]) \
        : "r"((a)[0]), "r"((a)[1]), "r"((a)[2]), "r"((a)[3]), \
          "r"((b)[0]), "r"((b)[1]))

// ===== 256-thread path (node/pre): K=32 chunk, warp tile 64x64 =====
template <int SA>
__device__ __forceinline__ void gemm_chunk_h(const __half* __restrict__ Ac,
                                             const __half* __restrict__ Bc,
                                             float (&c)[4][8][4],
                                             int wm, int wn, int g, int t) {
#pragma unroll
    for (int s = 0; s < 2; s++) {
        int kb = s * 16 + 2 * t;
        uint32_t a[4][4];
#pragma unroll
        for (int i = 0; i < 4; i++) {
            const __half* ap = Ac + (wm * 64 + i * 16 + g) * SA + kb;
            a[i][0] = *(const uint32_t*)(ap);
            a[i][1] = *(const uint32_t*)(ap + 8 * SA);
            a[i][2] = *(const uint32_t*)(ap + 8);
            a[i][3] = *(const uint32_t*)(ap + 8 * SA + 8);
        }
        uint32_t b[8][2];
#pragma unroll
        for (int j = 0; j < 8; j++) {
            const __half* bp = Bc + (wn * 64 + j * 8 + g) * 40 + kb;
            b[j][0] = *(const uint32_t*)(bp);
            b[j][1] = *(const uint32_t*)(bp + 8);
        }
#pragma unroll
        for (int i = 0; i < 4; i++)
#pragma unroll
            for (int j = 0; j < 8; j++)
                MMA_H(c[i][j], a[i], b[j]);
    }
}

// ===== 512-thread path (edge): K=64 chunk, warp tile 64x32, A stride 264 =====
__device__ __forceinline__ void gemm_chunk64(const __half* __restrict__ Ac,
                                             const __half* __restrict__ Bc,
                                             float (&c)[4][4][4],
                                             int wm, int wn, int g, int t) {
#pragma unroll
    for (int s = 0; s < 4; s++) {
        int kb = s * 16 + 2 * t;
        uint32_t a[4][4];
#pragma unroll
        for (int i = 0; i < 4; i++) {
            const __half* ap = Ac + (wm * 64 + i * 16 + g) * 264 + kb;
            a[i][0] = *(const uint32_t*)(ap);
            a[i][1] = *(const uint32_t*)(ap + 8 * 264);
            a[i][2] = *(const uint32_t*)(ap + 8);
            a[i][3] = *(const uint32_t*)(ap + 8 * 264 + 8);
        }
        uint32_t b[4][2];
#pragma unroll
        for (int j = 0; j < 4; j++) {
            const __half* bp = Bc + (wn * 32 + j * 8 + g) * 72 + kb;
            b[j][0] = *(const uint32_t*)(bp);
            b[j][1] = *(const uint32_t*)(bp + 8);
        }
#pragma unroll
        for (int i = 0; i < 4; i++)
#pragma unroll
            for (int j = 0; j < 4; j++)
                MMA_H(c[i][j], a[i], b[j]);
    }
}

__device__ __forceinline__ void init_bias8(float (&c)[4][8][4], const float* bs, int wn, int t) {
#pragma unroll
    for (int j = 0; j < 8; j++) {
        int col = wn * 64 + j * 8 + 2 * t;
        float b0 = bs[col], b1 = bs[col + 1];
#pragma unroll
        for (int i = 0; i < 4; i++) {
            c[i][j][0] = b0; c[i][j][1] = b1; c[i][j][2] = b0; c[i][j][3] = b1;
        }
    }
}
__device__ __forceinline__ void init_bias4(float (&c)[4][4][4], const float* bs, int wn, int t) {
#pragma unroll
    for (int j = 0; j < 4; j++) {
        int col = wn * 32 + j * 8 + 2 * t;
        float b0 = bs[col], b1 = bs[col + 1];
#pragma unroll
        for (int i = 0; i < 4; i++) {
            c[i][j][0] = b0; c[i][j][1] = b1; c[i][j][2] = b0; c[i][j][3] = b1;
        }
    }
}

__device__ __forceinline__ void store_silu8(const float (&c)[4][8][4], __half* A2,
                                            int wm, int wn, int g, int t) {
#pragma unroll
    for (int i = 0; i < 4; i++) {
        int r0 = wm * 64 + i * 16 + g;
#pragma unroll
        for (int j = 0; j < 8; j++) {
            int col = wn * 64 + j * 8 + 2 * t;
            *(__half2*)(A2 + r0 * 264 + col) =
                __floats2half2_rn(silu_f(c[i][j][0]), silu_f(c[i][j][1]));
            *(__half2*)(A2 + (r0 + 8) * 264 + col) =
                __floats2half2_rn(silu_f(c[i][j][2]), silu_f(c[i][j][3]));
        }
    }
}
__device__ __forceinline__ void store_silu4(const float (&c)[4][4][4], __half* A2,
                                            int wm, int wn, int g, int t) {
#pragma unroll
    for (int i = 0; i < 4; i++) {
        int r0 = wm * 64 + i * 16 + g;
#pragma unroll
        for (int j = 0; j < 4; j++) {
            int col = wn * 32 + j * 8 + 2 * t;
            *(__half2*)(A2 + r0 * 264 + col) =
                __floats2half2_rn(silu_f(c[i][j][0]), silu_f(c[i][j][1]));
            *(__half2*)(A2 + (r0 + 8) * 264 + col) =
                __floats2half2_rn(silu_f(c[i][j][2]), silu_f(c[i][j][3]));
        }
    }
}

// ---------------- prep kernels ----------------
__global__ void round_h_kernel(const float* __restrict__ h) {
    int i = blockIdx.x * blockDim.x + threadIdx.x;
    if (i < NN * 256) g_hh[i] = __float2half_rn(h[i]);
}
__global__ void round_agg_kernel() {
    int i = blockIdx.x * blockDim.x + threadIdx.x;
    if (i < NN * 256) g_aggh[i] = __float2half_rn(g_agg[i]);
}
__global__ void pack_we1(const float* __restrict__ We1) {
    int i = blockIdx.x * blockDim.x + threadIdx.x;
    if (i < 256 * 512) {
        int n = i >> 9, k = i & 511;
        __half v = __float2half_rn(We1[n * 513 + k]);
        if (k < 256) g_We1ah[n * 256 + k] = v;
        else         g_We1bh[n * 256 + (k - 256)] = v;
    }
    if (i < 256) g_w512[i] = We1[i * 513 + 512];
}
__global__ void pack_half(const float* __restrict__ W, __half* __restrict__ Wh, int count) {
    int i = blockIdx.x * blockDim.x + threadIdx.x;
    if (i < count) Wh[i] = __float2half_rn(W[i]);
}

// ---------------- precompute kernel: P = h @ We1{a,b}^T (K=256, fp32 out) ----------------
__global__ __launch_bounds__(256, 1) void pre_kernel() {
    extern __shared__ char smem[];
    __half* A1s = (__half*)(smem + N_A1);
    __half* Bsm = (__half*)(smem + N_B);
    int* idx = (int*)(smem + P_IDX);

    const __half* Wh = (blockIdx.y == 0) ? g_We1ah : g_We1bh;
    float* P = (blockIdx.y == 0) ? g_P1 : g_P2;

    const int tid = threadIdx.x;
    const int warp = tid >> 5, lane = tid & 31;
    const int wm = warp >> 2, wn = warp & 3, g = lane >> 2, t = lane & 3;
    const int base = blockIdx.x * 128;
    const uint32_t sbase = smem_u32(smem);
    const uint32_t a1u = sbase + N_A1, bu = sbase + N_B;

    if (tid < 128) {
        int n = base + tid;
        idx[tid] = (n < NN) ? n : 0;
    }
    __syncthreads();

    float c[4][8][4];
#pragma unroll
    for (int i = 0; i < 4; i++)
#pragma unroll
        for (int j = 0; j < 8; j++) {
            c[i][j][0] = 0.f; c[i][j][1] = 0.f; c[i][j][2] = 0.f; c[i][j][3] = 0.f;
        }

    auto stageA = [&](int kc, int buf) {
#pragma unroll
        for (int it = 0; it < 2; it++) {
            int v = it * 256 + tid;
            int r = v >> 2, seg = v & 3;
            cpa16(a1u + (uint32_t)(buf * 10240 + r * 80 + seg * 16),
                  g_hh + (size_t)idx[r] * 256 + kc * 32 + seg * 8);
        }
    };
    auto stageB = [&](int kc, int buf) {
#pragma unroll
        for (int it = 0; it < 4; it++) {
            int v = it * 256 + tid;
            int n = v >> 2, seg = v & 3;
            cpa16(bu + (uint32_t)(buf * 20480 + n * 80 + seg * 16),
                  Wh + (size_t)n * 256 + kc * 32 + seg * 8);
        }
    };

    stageA(0, 0); stageB(0, 0); cpcommit();
    for (int kc = 0; kc < 8; kc++) {
        cpwait0();
        __syncthreads();
        if (kc + 1 < 8) { stageA(kc + 1, (kc + 1) & 1); stageB(kc + 1, (kc + 1) & 1); cpcommit(); }
        gemm_chunk_h<40>(A1s + (kc & 1) * 5120, Bsm + (kc & 1) * 10240, c, wm, wn, g, t);
    }

#pragma unroll
    for (int i = 0; i < 4; i++) {
        int r0 = wm * 64 + i * 16 + g;
        int n0 = base + r0, n1 = base + r0 + 8;
#pragma unroll
        for (int j = 0; j < 8; j++) {
            int col = wn * 64 + j * 8 + 2 * t;
            if (n0 < NN) {
                P[(size_t)n0 * 256 + col]     = c[i][j][0];
                P[(size_t)n0 * 256 + col + 1] = c[i][j][1];
            }
            if (n1 < NN) {
                P[(size_t)n1 * 256 + col]     = c[i][j][2];
                P[(size_t)n1 * 256 + col + 1] = c[i][j][3];
            }
        }
    }
}

// ---------------- edge kernel (512 threads, K=64 chunks, warp tile 64x32) ----------------
__global__ __launch_bounds__(512, 1) void edge_kernel(
    const float* __restrict__ coordp, const int* __restrict__ ei,
    const float* __restrict__ be1, const float* __restrict__ be2,
    const float* __restrict__ bc1, const float* __restrict__ wc2) {
    extern __shared__ char smem[];
    __half* A2  = (__half*)(smem + E_A2);
    __half* Bsm = (__half*)(smem + E_B);
    int* rs = (int*)(smem + E_RS);
    int* cs = (int*)(smem + E_CS);
    float4* cd = (float4*)(smem + E_CD);
    float* phis = (float*)(smem + E_PHI);
    float* be1s = (float*)(smem + E_BE1);
    float* w512s = (float*)(smem + E_W512);
    float* be2s = (float*)(smem + E_BE2);
    float* bc1s = (float*)(smem + E_BC1);
    float* wc2s = (float*)(smem + E_WC2);

    const int tid = threadIdx.x;
    const int warp = tid >> 5, lane = tid & 31;
    const int wm = warp >> 3, wn = warp & 7, g = lane >> 2, t = lane & 3;
    const int ebase = blockIdx.x * 128;
    const uint32_t sbase = smem_u32(smem);
    const uint32_t bu = sbase + E_B;

    if (tid < 128) {
        int r = ei[ebase + tid], c = ei[NE + ebase + tid];
        rs[tid] = r; cs[tid] = c;
        float dx = coordp[r * 3 + 0] - coordp[c * 3 + 0];
        float dy = coordp[r * 3 + 1] - coordp[c * 3 + 1];
        float dz = coordp[r * 3 + 2] - coordp[c * 3 + 2];
        cd[tid] = make_float4(dx, dy, dz, dx * dx + dy * dy + dz * dz);
        phis[tid] = 0.f;
    }
    if (tid < 256) {
        be1s[tid] = be1[tid]; w512s[tid] = g_w512[tid];
        be2s[tid] = be2[tid]; bc1s[tid] = bc1[tid]; wc2s[tid] = wc2[tid];
    }
    __syncthreads();

    // stage one K=64 B chunk: 256 rows x 64 halves, row stride 72 halves (144 B)
    auto stageB = [&](const __half* __restrict__ Wh, int kc, int buf) {
#pragma unroll
        for (int it = 0; it < 4; it++) {
            int v = it * 512 + tid;
            int n = v >> 3, seg = v & 7;
            cpa16(bu + (uint32_t)(buf * 36864 + n * 144 + seg * 16),
                  Wh + (size_t)n * 256 + kc * 64 + seg * 8);
        }
    };

    stageB(g_We2h, 0, 0); cpcommit();

    // prologue: A2 = half(silu(P1[row] + P2[col] + radial*w512 + be1))
#pragma unroll
    for (int it = 0; it < 16; it++) {
        int v = it * 512 + tid;
        int r = v >> 6, k4 = (v & 63) << 2;
        float4 a = *(const float4*)(g_P1 + (size_t)rs[r] * 256 + k4);
        float4 b = *(const float4*)(g_P2 + (size_t)cs[r] * 256 + k4);
        float4 w = *(const float4*)(w512s + k4);
        float4 bb = *(const float4*)(be1s + k4);
        float rad = cd[r].w;
        *(__half2*)(A2 + r * 264 + k4) =
            __floats2half2_rn(silu_f(a.x + b.x + rad * w.x + bb.x),
                              silu_f(a.y + b.y + rad * w.y + bb.y));
        *(__half2*)(A2 + r * 264 + k4 + 2) =
            __floats2half2_rn(silu_f(a.z + b.z + rad * w.z + bb.z),
                              silu_f(a.w + b.w + rad * w.w + bb.w));
    }

    float c[4][4][4];

    // ---- GEMM2: m @ We2^T (K=256, 4 chunks of 64) ----
    init_bias4(c, be2s, wn, t);
    for (int kc = 0; kc < 4; kc++) {
        cpwait0();
        __syncthreads();
        if (kc + 1 < 4) { stageB(g_We2h, kc + 1, (kc + 1) & 1); cpcommit(); }
        gemm_chunk64(A2 + kc * 64, Bsm + (kc & 1) * 18432, c, wm, wn, g, t);
    }
    __syncthreads();
    store_silu4(c, A2, wm, wn, g, t);   // A2 = edge_feat (half)
    stageB(g_Wc1h, 0, 0); cpcommit();

    // ---- GEMM3: edge_feat @ Wc1^T (K=256, 4 chunks) ----
    init_bias4(c, bc1s, wn, t);
    for (int kc = 0; kc < 4; kc++) {
        cpwait0();
        __syncthreads();
        if (kc + 1 < 4) { stageB(g_Wc1h, kc + 1, (kc + 1) & 1); cpcommit(); }
        gemm_chunk64(A2 + kc * 64, Bsm + (kc & 1) * 18432, c, wm, wn, g, t);
    }

    // phi_x[e] = silu(C3) . wc2  (fp32)
    {
        float pr[8];
#pragma unroll
        for (int k = 0; k < 8; k++) pr[k] = 0.f;
#pragma unroll
        for (int i = 0; i < 4; i++)
#pragma unroll
            for (int j = 0; j < 4; j++) {
                int col = wn * 32 + j * 8 + 2 * t;
                float w0 = wc2s[col], w1 = wc2s[col + 1];
                pr[i * 2]     += silu_f(c[i][j][0]) * w0 + silu_f(c[i][j][1]) * w1;
                pr[i * 2 + 1] += silu_f(c[i][j][2]) * w0 + silu_f(c[i][j][3]) * w1;
            }
#pragma unroll
        for (int k = 0; k < 8; k++) {
            pr[k] += __shfl_xor_sync(0xffffffffu, pr[k], 1);
            pr[k] += __shfl_xor_sync(0xffffffffu, pr[k], 2);
        }
        if (t == 0) {
#pragma unroll
            for (int i = 0; i < 4; i++) {
                atomicAdd(&phis[wm * 64 + i * 16 + g], pr[i * 2]);
                atomicAdd(&phis[wm * 64 + i * 16 + g + 8], pr[i * 2 + 1]);
            }
        }
    }
    __syncthreads();

    // coord aggregation
    if (tid < 128) {
        float4 d = cd[tid];
        float p = phis[tid];
        red4(&g_cagg[(size_t)rs[tid] * 4], d.x * p, d.y * p, d.z * p, 1.0f);
    }
    // feature aggregation: edge_feat (half) -> fp32 red4
#pragma unroll
    for (int it = 0; it < 16; it++) {
        int v = it * 512 + tid;
        int r = v >> 6, c4 = (v & 63) << 2;
        __half2 p0 = *(const __half2*)(A2 + r * 264 + c4);
        __half2 p1 = *(const __half2*)(A2 + r * 264 + c4 + 2);
        red4(&g_agg[(size_t)rs[r] * 256 + c4],
             __low2float(p0), __high2float(p0), __low2float(p1), __high2float(p1));
    }
}

// ---------------- node kernel ----------------
__global__ __launch_bounds__(256, 1) void node_kernel(
    const float* __restrict__ h, const float* __restrict__ bn1,
    const float* __restrict__ bn2, float* __restrict__ out) {
    extern __shared__ char smem[];
    __half* A1s = (__half*)(smem + N_A1);
    __half* Bsm = (__half*)(smem + N_B);
    __half* A2  = (__half*)(smem + N_A2);
    int* idx = (int*)(smem + N_IDX);
    float* b1s = (float*)(smem + N_B1);
    float* b2s = (float*)(smem + N_B2);

    const int tid = threadIdx.x;
    const int warp = tid >> 5, lane = tid & 31;
    const int wm = warp >> 2, wn = warp & 3, g = lane >> 2, t = lane & 3;
    const int base = blockIdx.x * 128;
    const uint32_t sbase = smem_u32(smem);
    const uint32_t a1u = sbase + N_A1, bu = sbase + N_B;

    if (tid < 128) {
        int n = base + tid;
        idx[tid] = (n < NN) ? n : 0;
    }
    b1s[tid] = bn1[tid]; b2s[tid] = bn2[tid];
    __syncthreads();

    float c[4][8][4];

    auto stageA = [&](int kc, int buf) {
        const __half* basep = (kc < 8) ? g_hh : g_aggh;
        int koff = (kc & 7) * 32;
#pragma unroll
        for (int it = 0; it < 2; it++) {
            int v = it * 256 + tid;
            int r = v >> 2, seg = v & 3;
            cpa16(a1u + (uint32_t)(buf * 10240 + r * 80 + seg * 16),
                  basep + (size_t)idx[r] * 256 + koff + seg * 8);
        }
    };
    auto stageB = [&](const __half* __restrict__ Wh, int kstride, int kc, int buf) {
#pragma unroll
        for (int it = 0; it < 4; it++) {
            int v = it * 256 + tid;
            int n = v >> 2, seg = v & 3;
            cpa16(bu + (uint32_t)(buf * 20480 + n * 80 + seg * 16),
                  Wh + (size_t)n * kstride + kc * 32 + seg * 8);
        }
    };

    // GEMM1: [h | agg] @ Wn1^T (K=512, 16 chunks)
    init_bias8(c, b1s, wn, t);
    stageA(0, 0); stageB(g_Wn1h, 512, 0, 0); cpcommit();
    for (int kc = 0; kc < 16; kc++) {
        cpwait0();
        __syncthreads();
        if (kc + 1 < 16) { stageA(kc + 1, (kc + 1) & 1); stageB(g_Wn1h, 512, kc + 1, (kc + 1) & 1); cpcommit(); }
        gemm_chunk_h<40>(A1s + (kc & 1) * 5120, Bsm + (kc & 1) * 10240, c, wm, wn, g, t);
    }
    __syncthreads();
    store_silu8(c, A2, wm, wn, g, t);
    stageB(g_Wn2h, 256, 0, 0); cpcommit();

    // GEMM2: @ Wn2^T (K=256, 8 chunks), + bn2 + residual h
    init_bias8(c, b2s, wn, t);
    for (int kc = 0; kc < 8; kc++) {
        cpwait0();
        __syncthreads();
        if (kc + 1 < 8) { stageB(g_Wn2h, 256, kc + 1, (kc + 1) & 1); cpcommit(); }
        gemm_chunk_h<264>(A2 + kc * 32, Bsm + (kc & 1) * 10240, c, wm, wn, g, t);
    }
#pragma unroll
    for (int i = 0; i < 4; i++) {
        int r0 = wm * 64 + i * 16 + g;
        int n0 = base + r0, n1 = base + r0 + 8;
#pragma unroll
        for (int j = 0; j < 8; j++) {
            int col = wn * 64 + j * 8 + 2 * t;
            if (n0 < NN) {
                out[(size_t)n0 * 256 + col]     = c[i][j][0] + h[(size_t)n0 * 256 + col];
                out[(size_t)n0 * 256 + col + 1] = c[i][j][1] + h[(size_t)n0 * 256 + col + 1];
            }
            if (n1 < NN) {
                out[(size_t)n1 * 256 + col]     = c[i][j][2] + h[(size_t)n1 * 256 + col];
                out[(size_t)n1 * 256 + col + 1] = c[i][j][3] + h[(size_t)n1 * 256 + col + 1];
            }
        }
    }
}

// ---------------- coord finish ----------------
__global__ void coord_kernel(const float* __restrict__ coordp, float* __restrict__ out) {
    int n = blockIdx.x * blockDim.x + threadIdx.x;
    if (n < NN) {
        float cnt = g_cagg[n * 4 + 3];
        float s = 1.0f / fmaxf(cnt, 1.0f);
        float* o = out + (size_t)NN * 256 + (size_t)n * 3;
        o[0] = coordp[n * 3 + 0] + g_cagg[n * 4 + 0] * s;
        o[1] = coordp[n * 3 + 1] + g_cagg[n * 4 + 1] * s;
        o[2] = coordp[n * 3 + 2] + g_cagg[n * 4 + 2] * s;
    }
}

// ---------------- host ----------------
extern "C" void kernel_launch(void* const* d_in, const int* in_sizes, int n_in,
                              void* d_out, int out_size) {
    (void)in_sizes; (void)n_in; (void)out_size;
    const float* h     = (const float*)d_in[0];
    const int*   ei    = (const int*)d_in[1];
    const float* coord = (const float*)d_in[2];
    const float* We1   = (const float*)d_in[3];
    const float* be1   = (const float*)d_in[4];
    const float* We2   = (const float*)d_in[5];
    const float* be2   = (const float*)d_in[6];
    const float* Wn1   = (const float*)d_in[7];
    const float* bn1   = (const float*)d_in[8];
    const float* Wn2   = (const float*)d_in[9];
    const float* bn2   = (const float*)d_in[10];
    const float* Wc1   = (const float*)d_in[11];
    const float* bc1   = (const float*)d_in[12];
    const float* Wc2   = (const float*)d_in[13];
    float* out = (float*)d_out;

    cudaFuncSetAttribute(edge_kernel, cudaFuncAttributeMaxDynamicSharedMemorySize, E_SMEM);
    cudaFuncSetAttribute(node_kernel, cudaFuncAttributeMaxDynamicSharedMemorySize, N_SMEM);
    cudaFuncSetAttribute(pre_kernel,  cudaFuncAttributeMaxDynamicSharedMemorySize, P_SMEM);

    void* agg_p = nullptr; void* cagg_p = nullptr;
    cudaGetSymbolAddress(&agg_p, g_agg);
    cudaGetSymbolAddress(&cagg_p, g_cagg);
    cudaMemsetAsync(agg_p, 0, sizeof(float) * (size_t)NN * 256, 0);
    cudaMemsetAsync(cagg_p, 0, sizeof(float) * (size_t)NN * 4, 0);

    __half* we2h; __half* wc1h; __half* wn1h; __half* wn2h;
    cudaGetSymbolAddress((void**)&we2h, g_We2h);
    cudaGetSymbolAddress((void**)&wc1h, g_Wc1h);
    cudaGetSymbolAddress((void**)&wn1h, g_Wn1h);
    cudaGetSymbolAddress((void**)&wn2h, g_Wn2h);

    pack_we1<<<(256 * 512 + 255) / 256, 256>>>(We1);
    pack_half<<<(256 * 256 + 255) / 256, 256>>>(We2, we2h, 256 * 256);
    pack_half<<<(256 * 256 + 255) / 256, 256>>>(Wc1, wc1h, 256 * 256);
    pack_half<<<(256 * 512 + 255) / 256, 256>>>(Wn1, wn1h, 256 * 512);
    pack_half<<<(256 * 256 + 255) / 256, 256>>>(Wn2, wn2h, 256 * 256);
    round_h_kernel<<<(NN * 256 + 255) / 256, 256>>>(h);

    pre_kernel<<<dim3((NN + 127) / 128, 2), 256, P_SMEM>>>();

    edge_kernel<<<NE / 128, 512, E_SMEM>>>(coord, ei, be1, be2, bc1, Wc2);

    round_agg_kernel<<<(NN * 256 + 255) / 256, 256>>>();

    node_kernel<<<(NN + 127) / 128, 256, N_SMEM>>>(h, bn1, bn2, out);
    coord_kernel<<<(NN + 255) / 256, 256>>>(coord, out);
}

// round 9
// speedup vs baseline: 2.2313x; 1.0717x over previous
#include <cuda_runtime.h>
#include <cuda_fp16.h>
#include <cstdint>
#include <cstddef>

#define NN 50000
#define NE 800000

// ---------------- scratch (no allocation allowed) ----------------
__device__ float  g_agg[NN * 256];     // fp32 segment-sum of edge_feat
__device__ __half g_aggh[NN * 256];    // half copy for node GEMM1
__device__ float  g_cagg[NN * 4];      // {sum dx*phi, dy*phi, dz*phi, count}
__device__ __half g_hh[NN * 256];      // half-rounded h
__device__ float  g_P1[NN * 256];      // h @ We1[:, :256]^T   (fp32)
__device__ float  g_P2[NN * 256];      // h @ We1[:, 256:512]^T (fp32)
__device__ __half g_We1ah[256 * 256];  // [n][k] half, k = 0..255
__device__ __half g_We1bh[256 * 256];  // [n][k] half, k = 256..511
__device__ float  g_w512[256];         // We1[:, 512] (radial weight, fp32)
__device__ __half g_We2h[256 * 256];   // [n][k] half
__device__ __half g_Wc1h[256 * 256];
__device__ __half g_Wn1h[256 * 512];
__device__ __half g_Wn2h[256 * 256];

// ---------------- edge kernel smem (bytes) ----------------
#define E_A2   0         // 128 x 264 halves = 67584
#define E_B    67584     // 2 x 256 x 72 halves = 73728
#define E_RS   141312    // 128 ints
#define E_CS   141824
#define E_CD   142336    // 128 float4
#define E_PHI  144384    // 128 floats
#define E_BE1  144896    // 256 floats
#define E_W512 145920
#define E_BE2  146944
#define E_BC1  147968
#define E_WC2  148992
#define E_SMEM 150016

// ---------------- node kernel smem (512 threads, K=64 chunks) ----------------
#define N_A1   0         // 2 x 128 x 72 halves = 36864
#define N_B    36864     // 2 x 256 x 72 halves = 73728
#define N_A2   110592    // 128 x 264 halves = 67584
#define N_IDX  178176    // 128 ints
#define N_B1   178688    // 256 floats
#define N_B2   179712    // 256 floats
#define N_SMEM 180736

// ---------------- pre kernel smem (256 threads, K=32 chunks) ----------------
#define P_A1   0         // 2 x 128 x 40 halves = 20480
#define P_B    20480     // 2 x 256 x 40 halves = 40960
#define P_IDX  61440
#define P_SMEM 61952

// ---------------- helpers ----------------
__device__ __forceinline__ uint32_t smem_u32(const void* p) {
    uint32_t a;
    asm("{ .reg .u64 t; cvta.to.shared.u64 t, %1; cvt.u32.u64 %0, t; }" : "=r"(a) : "l"(p));
    return a;
}
__device__ __forceinline__ void cpa16(uint32_t s, const void* g) {
    asm volatile("cp.async.cg.shared.global [%0], [%1], 16;" :: "r"(s), "l"(g));
}
__device__ __forceinline__ void cpcommit() { asm volatile("cp.async.commit_group;"); }
__device__ __forceinline__ void cpwait0() { asm volatile("cp.async.wait_group 0;"); }

__device__ __forceinline__ float silu_f(float x) { return x / (1.0f + __expf(-x)); }
__device__ __forceinline__ void red4(float* gp, float x, float y, float z, float w) {
    asm volatile("red.global.add.v4.f32 [%0], {%1,%2,%3,%4};"
                 :: "l"(gp), "f"(x), "f"(y), "f"(z), "f"(w) : "memory");
}

#define MMA_H(c, a, b) \
    asm volatile( \
        "mma.sync.aligned.m16n8k16.row.col.f32.f16.f16.f32 " \
        "{%0,%1,%2,%3},{%4,%5,%6,%7},{%8,%9},{%0,%1,%2,%3};" \
        : "+f"((c)[0]), "+f"((c)[1]), "+f"((c)[2]), "+f"((c)[3]) \
        : "r"((a)[0]), "r"((a)[1]), "r"((a)[2]), "r"((a)[3]), \
          "r"((b)[0]), "r"((b)[1]))

#define LDSM4(r0, r1, r2, r3, addr) \
    asm volatile("ldmatrix.sync.aligned.m8n8.x4.shared.b16 {%0,%1,%2,%3}, [%4];" \
                 : "=r"(r0), "=r"(r1), "=r"(r2), "=r"(r3) : "r"(addr))

// ===== K=64 chunk, warp tile 64x32, ldmatrix loads. =====
// A: halves @ aAddr (smem byte address), row stride SA halves.
// B: halves @ bAddr, row stride 72 halves (256 n-rows x 64 k).
template <int SA>
__device__ __forceinline__ void gemm_ldsm(uint32_t aAddr, uint32_t bAddr,
                                          float (&c)[4][4][4],
                                          int wm, int wn, int lane) {
    const int arow = wm * 64 + (lane & 15);
    const int kA = ((lane >> 4) & 1) * 8;
    const int bn = wn * 32 + (lane & 7) + ((lane >> 4) & 1) * 8;
    const int kB = ((lane >> 3) & 1) * 8;
#pragma unroll
    for (int s = 0; s < 4; s++) {
        uint32_t a[4][4];
#pragma unroll
        for (int i = 0; i < 4; i++) {
            uint32_t ad = aAddr + (uint32_t)(((arow + i * 16) * SA + s * 16 + kA) * 2);
            LDSM4(a[i][0], a[i][1], a[i][2], a[i][3], ad);
        }
        uint32_t b[4][2];
#pragma unroll
        for (int jp = 0; jp < 2; jp++) {
            uint32_t bd = bAddr + (uint32_t)(((bn + jp * 16) * 72 + s * 16 + kB) * 2);
            LDSM4(b[2 * jp][0], b[2 * jp][1], b[2 * jp + 1][0], b[2 * jp + 1][1], bd);
        }
#pragma unroll
        for (int i = 0; i < 4; i++)
#pragma unroll
            for (int j = 0; j < 4; j++)
                MMA_H(c[i][j], a[i], b[j]);
    }
}

// ===== 256-thread pre kernel path: K=32 chunk, warp tile 64x64 (scalar loads) =====
template <int SA>
__device__ __forceinline__ void gemm_chunk_h(const __half* __restrict__ Ac,
                                             const __half* __restrict__ Bc,
                                             float (&c)[4][8][4],
                                             int wm, int wn, int g, int t) {
#pragma unroll
    for (int s = 0; s < 2; s++) {
        int kb = s * 16 + 2 * t;
        uint32_t a[4][4];
#pragma unroll
        for (int i = 0; i < 4; i++) {
            const __half* ap = Ac + (wm * 64 + i * 16 + g) * SA + kb;
            a[i][0] = *(const uint32_t*)(ap);
            a[i][1] = *(const uint32_t*)(ap + 8 * SA);
            a[i][2] = *(const uint32_t*)(ap + 8);
            a[i][3] = *(const uint32_t*)(ap + 8 * SA + 8);
        }
        uint32_t b[8][2];
#pragma unroll
        for (int j = 0; j < 8; j++) {
            const __half* bp = Bc + (wn * 64 + j * 8 + g) * 40 + kb;
            b[j][0] = *(const uint32_t*)(bp);
            b[j][1] = *(const uint32_t*)(bp + 8);
        }
#pragma unroll
        for (int i = 0; i < 4; i++)
#pragma unroll
            for (int j = 0; j < 8; j++)
                MMA_H(c[i][j], a[i], b[j]);
    }
}

__device__ __forceinline__ void init_bias4(float (&c)[4][4][4], const float* bs, int wn, int t) {
#pragma unroll
    for (int j = 0; j < 4; j++) {
        int col = wn * 32 + j * 8 + 2 * t;
        float b0 = bs[col], b1 = bs[col + 1];
#pragma unroll
        for (int i = 0; i < 4; i++) {
            c[i][j][0] = b0; c[i][j][1] = b1; c[i][j][2] = b0; c[i][j][3] = b1;
        }
    }
}

__device__ __forceinline__ void store_silu4(const float (&c)[4][4][4], __half* A2,
                                            int wm, int wn, int g, int t) {
#pragma unroll
    for (int i = 0; i < 4; i++) {
        int r0 = wm * 64 + i * 16 + g;
#pragma unroll
        for (int j = 0; j < 4; j++) {
            int col = wn * 32 + j * 8 + 2 * t;
            *(__half2*)(A2 + r0 * 264 + col) =
                __floats2half2_rn(silu_f(c[i][j][0]), silu_f(c[i][j][1]));
            *(__half2*)(A2 + (r0 + 8) * 264 + col) =
                __floats2half2_rn(silu_f(c[i][j][2]), silu_f(c[i][j][3]));
        }
    }
}

// ---------------- prep kernels ----------------
__global__ void round_h_kernel(const float* __restrict__ h) {
    int i = blockIdx.x * blockDim.x + threadIdx.x;
    if (i < NN * 256) g_hh[i] = __float2half_rn(h[i]);
}
__global__ void round_agg_kernel() {
    int i = blockIdx.x * blockDim.x + threadIdx.x;
    if (i < NN * 256) g_aggh[i] = __float2half_rn(g_agg[i]);
}
__global__ void pack_we1(const float* __restrict__ We1) {
    int i = blockIdx.x * blockDim.x + threadIdx.x;
    if (i < 256 * 512) {
        int n = i >> 9, k = i & 511;
        __half v = __float2half_rn(We1[n * 513 + k]);
        if (k < 256) g_We1ah[n * 256 + k] = v;
        else         g_We1bh[n * 256 + (k - 256)] = v;
    }
    if (i < 256) g_w512[i] = We1[i * 513 + 512];
}
__global__ void pack_half(const float* __restrict__ W, __half* __restrict__ Wh, int count) {
    int i = blockIdx.x * blockDim.x + threadIdx.x;
    if (i < count) Wh[i] = __float2half_rn(W[i]);
}

// ---------------- precompute kernel: P = h @ We1{a,b}^T (K=256, fp32 out) ----------------
__global__ __launch_bounds__(256, 1) void pre_kernel() {
    extern __shared__ char smem[];
    __half* A1s = (__half*)(smem + P_A1);
    __half* Bsm = (__half*)(smem + P_B);
    int* idx = (int*)(smem + P_IDX);

    const __half* Wh = (blockIdx.y == 0) ? g_We1ah : g_We1bh;
    float* P = (blockIdx.y == 0) ? g_P1 : g_P2;

    const int tid = threadIdx.x;
    const int warp = tid >> 5, lane = tid & 31;
    const int wm = warp >> 2, wn = warp & 3, g = lane >> 2, t = lane & 3;
    const int base = blockIdx.x * 128;
    const uint32_t sbase = smem_u32(smem);
    const uint32_t a1u = sbase + P_A1, bu = sbase + P_B;

    if (tid < 128) {
        int n = base + tid;
        idx[tid] = (n < NN) ? n : 0;
    }
    __syncthreads();

    float c[4][8][4];
#pragma unroll
    for (int i = 0; i < 4; i++)
#pragma unroll
        for (int j = 0; j < 8; j++) {
            c[i][j][0] = 0.f; c[i][j][1] = 0.f; c[i][j][2] = 0.f; c[i][j][3] = 0.f;
        }

    auto stageA = [&](int kc, int buf) {
#pragma unroll
        for (int it = 0; it < 2; it++) {
            int v = it * 256 + tid;
            int r = v >> 2, seg = v & 3;
            cpa16(a1u + (uint32_t)(buf * 10240 + r * 80 + seg * 16),
                  g_hh + (size_t)idx[r] * 256 + kc * 32 + seg * 8);
        }
    };
    auto stageB = [&](int kc, int buf) {
#pragma unroll
        for (int it = 0; it < 4; it++) {
            int v = it * 256 + tid;
            int n = v >> 2, seg = v & 3;
            cpa16(bu + (uint32_t)(buf * 20480 + n * 80 + seg * 16),
                  Wh + (size_t)n * 256 + kc * 32 + seg * 8);
        }
    };

    stageA(0, 0); stageB(0, 0); cpcommit();
    for (int kc = 0; kc < 8; kc++) {
        cpwait0();
        __syncthreads();
        if (kc + 1 < 8) { stageA(kc + 1, (kc + 1) & 1); stageB(kc + 1, (kc + 1) & 1); cpcommit(); }
        gemm_chunk_h<40>(A1s + (kc & 1) * 5120, Bsm + (kc & 1) * 10240, c, wm, wn, g, t);
    }

#pragma unroll
    for (int i = 0; i < 4; i++) {
        int r0 = wm * 64 + i * 16 + g;
        int n0 = base + r0, n1 = base + r0 + 8;
#pragma unroll
        for (int j = 0; j < 8; j++) {
            int col = wn * 64 + j * 8 + 2 * t;
            if (n0 < NN) {
                P[(size_t)n0 * 256 + col]     = c[i][j][0];
                P[(size_t)n0 * 256 + col + 1] = c[i][j][1];
            }
            if (n1 < NN) {
                P[(size_t)n1 * 256 + col]     = c[i][j][2];
                P[(size_t)n1 * 256 + col + 1] = c[i][j][3];
            }
        }
    }
}

// ---------------- edge kernel (512 threads, K=64 chunks, ldmatrix) ----------------
__global__ __launch_bounds__(512, 1) void edge_kernel(
    const float* __restrict__ coordp, const int* __restrict__ ei,
    const float* __restrict__ be1, const float* __restrict__ be2,
    const float* __restrict__ bc1, const float* __restrict__ wc2) {
    extern __shared__ char smem[];
    __half* A2  = (__half*)(smem + E_A2);
    int* rs = (int*)(smem + E_RS);
    int* cs = (int*)(smem + E_CS);
    float4* cd = (float4*)(smem + E_CD);
    float* phis = (float*)(smem + E_PHI);
    float* be1s = (float*)(smem + E_BE1);
    float* w512s = (float*)(smem + E_W512);
    float* be2s = (float*)(smem + E_BE2);
    float* bc1s = (float*)(smem + E_BC1);
    float* wc2s = (float*)(smem + E_WC2);

    const int tid = threadIdx.x;
    const int warp = tid >> 5, lane = tid & 31;
    const int wm = warp >> 3, wn = warp & 7, g = lane >> 2, t = lane & 3;
    const int ebase = blockIdx.x * 128;
    const uint32_t sbase = smem_u32(smem);
    const uint32_t a2u = sbase + E_A2, bu = sbase + E_B;

    if (tid < 128) {
        int r = ei[ebase + tid], c = ei[NE + ebase + tid];
        rs[tid] = r; cs[tid] = c;
        float dx = coordp[r * 3 + 0] - coordp[c * 3 + 0];
        float dy = coordp[r * 3 + 1] - coordp[c * 3 + 1];
        float dz = coordp[r * 3 + 2] - coordp[c * 3 + 2];
        cd[tid] = make_float4(dx, dy, dz, dx * dx + dy * dy + dz * dz);
        phis[tid] = 0.f;
    }
    if (tid < 256) {
        be1s[tid] = be1[tid]; w512s[tid] = g_w512[tid];
        be2s[tid] = be2[tid]; bc1s[tid] = bc1[tid]; wc2s[tid] = wc2[tid];
    }
    __syncthreads();

    auto stageB = [&](const __half* __restrict__ Wh, int kc, int buf) {
#pragma unroll
        for (int it = 0; it < 4; it++) {
            int v = it * 512 + tid;
            int n = v >> 3, seg = v & 7;
            cpa16(bu + (uint32_t)(buf * 36864 + n * 144 + seg * 16),
                  Wh + (size_t)n * 256 + kc * 64 + seg * 8);
        }
    };

    stageB(g_We2h, 0, 0); cpcommit();

    // prologue: A2 = half(silu(P1[row] + P2[col] + radial*w512 + be1))
#pragma unroll
    for (int it = 0; it < 16; it++) {
        int v = it * 512 + tid;
        int r = v >> 6, k4 = (v & 63) << 2;
        float4 a = *(const float4*)(g_P1 + (size_t)rs[r] * 256 + k4);
        float4 b = *(const float4*)(g_P2 + (size_t)cs[r] * 256 + k4);
        float4 w = *(const float4*)(w512s + k4);
        float4 bb = *(const float4*)(be1s + k4);
        float rad = cd[r].w;
        *(__half2*)(A2 + r * 264 + k4) =
            __floats2half2_rn(silu_f(a.x + b.x + rad * w.x + bb.x),
                              silu_f(a.y + b.y + rad * w.y + bb.y));
        *(__half2*)(A2 + r * 264 + k4 + 2) =
            __floats2half2_rn(silu_f(a.z + b.z + rad * w.z + bb.z),
                              silu_f(a.w + b.w + rad * w.w + bb.w));
    }

    float c[4][4][4];

    // ---- GEMM2: m @ We2^T (K=256, 4 chunks of 64) ----
    init_bias4(c, be2s, wn, t);
    for (int kc = 0; kc < 4; kc++) {
        cpwait0();
        __syncthreads();
        if (kc + 1 < 4) { stageB(g_We2h, kc + 1, (kc + 1) & 1); cpcommit(); }
        gemm_ldsm<264>(a2u + kc * 128, bu + (kc & 1) * 36864, c, wm, wn, lane);
    }
    __syncthreads();
    store_silu4(c, A2, wm, wn, g, t);   // A2 = edge_feat (half)
    stageB(g_Wc1h, 0, 0); cpcommit();

    // ---- GEMM3: edge_feat @ Wc1^T (K=256, 4 chunks) ----
    init_bias4(c, bc1s, wn, t);
    for (int kc = 0; kc < 4; kc++) {
        cpwait0();
        __syncthreads();
        if (kc + 1 < 4) { stageB(g_Wc1h, kc + 1, (kc + 1) & 1); cpcommit(); }
        gemm_ldsm<264>(a2u + kc * 128, bu + (kc & 1) * 36864, c, wm, wn, lane);
    }

    // phi_x[e] = silu(C3) . wc2  (fp32)
    {
        float pr[8];
#pragma unroll
        for (int k = 0; k < 8; k++) pr[k] = 0.f;
#pragma unroll
        for (int i = 0; i < 4; i++)
#pragma unroll
            for (int j = 0; j < 4; j++) {
                int col = wn * 32 + j * 8 + 2 * t;
                float w0 = wc2s[col], w1 = wc2s[col + 1];
                pr[i * 2]     += silu_f(c[i][j][0]) * w0 + silu_f(c[i][j][1]) * w1;
                pr[i * 2 + 1] += silu_f(c[i][j][2]) * w0 + silu_f(c[i][j][3]) * w1;
            }
#pragma unroll
        for (int k = 0; k < 8; k++) {
            pr[k] += __shfl_xor_sync(0xffffffffu, pr[k], 1);
            pr[k] += __shfl_xor_sync(0xffffffffu, pr[k], 2);
        }
        if (t == 0) {
#pragma unroll
            for (int i = 0; i < 4; i++) {
                atomicAdd(&phis[wm * 64 + i * 16 + g], pr[i * 2]);
                atomicAdd(&phis[wm * 64 + i * 16 + g + 8], pr[i * 2 + 1]);
            }
        }
    }
    __syncthreads();

    // coord aggregation
    if (tid < 128) {
        float4 d = cd[tid];
        float p = phis[tid];
        red4(&g_cagg[(size_t)rs[tid] * 4], d.x * p, d.y * p, d.z * p, 1.0f);
    }
    // feature aggregation: edge_feat (half) -> fp32 red4
#pragma unroll
    for (int it = 0; it < 16; it++) {
        int v = it * 512 + tid;
        int r = v >> 6, c4 = (v & 63) << 2;
        __half2 p0 = *(const __half2*)(A2 + r * 264 + c4);
        __half2 p1 = *(const __half2*)(A2 + r * 264 + c4 + 2);
        red4(&g_agg[(size_t)rs[r] * 256 + c4],
             __low2float(p0), __high2float(p0), __low2float(p1), __high2float(p1));
    }
}

// ---------------- node kernel (512 threads, K=64 chunks, ldmatrix) ----------------
__global__ __launch_bounds__(512, 1) void node_kernel(
    const float* __restrict__ h, const float* __restrict__ bn1,
    const float* __restrict__ bn2, float* __restrict__ out) {
    extern __shared__ char smem[];
    __half* A2  = (__half*)(smem + N_A2);
    int* idx = (int*)(smem + N_IDX);
    float* b1s = (float*)(smem + N_B1);
    float* b2s = (float*)(smem + N_B2);

    const int tid = threadIdx.x;
    const int warp = tid >> 5, lane = tid & 31;
    const int wm = warp >> 3, wn = warp & 7, g = lane >> 2, t = lane & 3;
    const int base = blockIdx.x * 128;
    const uint32_t sbase = smem_u32(smem);
    const uint32_t a1u = sbase + N_A1, bu = sbase + N_B, a2u = sbase + N_A2;

    if (tid < 128) {
        int n = base + tid;
        idx[tid] = (n < NN) ? n : 0;
    }
    if (tid < 256) { b1s[tid] = bn1[tid]; b2s[tid] = bn2[tid]; }
    __syncthreads();

    // stage A chunk: 128 rows x 64 halves, row stride 72 halves
    auto stageA = [&](int kc, int buf) {
        const __half* basep = (kc < 4) ? g_hh : g_aggh;
        int koff = (kc & 3) * 64;
#pragma unroll
        for (int it = 0; it < 2; it++) {
            int v = it * 512 + tid;
            int r = v >> 3, seg = v & 7;
            cpa16(a1u + (uint32_t)(buf * 18432 + r * 144 + seg * 16),
                  basep + (size_t)idx[r] * 256 + koff + seg * 8);
        }
    };
    auto stageB = [&](const __half* __restrict__ Wh, int kstride, int kc, int buf) {
#pragma unroll
        for (int it = 0; it < 4; it++) {
            int v = it * 512 + tid;
            int n = v >> 3, seg = v & 7;
            cpa16(bu + (uint32_t)(buf * 36864 + n * 144 + seg * 16),
                  Wh + (size_t)n * kstride + kc * 64 + seg * 8);
        }
    };

    float c[4][4][4];

    // GEMM1: [h | agg] @ Wn1^T (K=512, 8 chunks of 64)
    init_bias4(c, b1s, wn, t);
    stageA(0, 0); stageB(g_Wn1h, 512, 0, 0); cpcommit();
    for (int kc = 0; kc < 8; kc++) {
        cpwait0();
        __syncthreads();
        if (kc + 1 < 8) {
            stageA(kc + 1, (kc + 1) & 1);
            stageB(g_Wn1h, 512, kc + 1, (kc + 1) & 1);
            cpcommit();
        }
        gemm_ldsm<72>(a1u + (kc & 1) * 18432, bu + (kc & 1) * 36864, c, wm, wn, lane);
    }
    __syncthreads();
    store_silu4(c, A2, wm, wn, g, t);
    stageB(g_Wn2h, 256, 0, 0); cpcommit();

    // GEMM2: @ Wn2^T (K=256, 4 chunks), + bn2 + residual h
    init_bias4(c, b2s, wn, t);
    for (int kc = 0; kc < 4; kc++) {
        cpwait0();
        __syncthreads();
        if (kc + 1 < 4) { stageB(g_Wn2h, 256, kc + 1, (kc + 1) & 1); cpcommit(); }
        gemm_ldsm<264>(a2u + kc * 128, bu + (kc & 1) * 36864, c, wm, wn, lane);
    }
#pragma unroll
    for (int i = 0; i < 4; i++) {
        int r0 = wm * 64 + i * 16 + g;
        int n0 = base + r0, n1 = base + r0 + 8;
#pragma unroll
        for (int j = 0; j < 4; j++) {
            int col = wn * 32 + j * 8 + 2 * t;
            if (n0 < NN) {
                out[(size_t)n0 * 256 + col]     = c[i][j][0] + h[(size_t)n0 * 256 + col];
                out[(size_t)n0 * 256 + col + 1] = c[i][j][1] + h[(size_t)n0 * 256 + col + 1];
            }
            if (n1 < NN) {
                out[(size_t)n1 * 256 + col]     = c[i][j][2] + h[(size_t)n1 * 256 + col];
                out[(size_t)n1 * 256 + col + 1] = c[i][j][3] + h[(size_t)n1 * 256 + col + 1];
            }
        }
    }
}

// ---------------- coord finish ----------------
__global__ void coord_kernel(const float* __restrict__ coordp, float* __restrict__ out) {
    int n = blockIdx.x * blockDim.x + threadIdx.x;
    if (n < NN) {
        float cnt = g_cagg[n * 4 + 3];
        float s = 1.0f / fmaxf(cnt, 1.0f);
        float* o = out + (size_t)NN * 256 + (size_t)n * 3;
        o[0] = coordp[n * 3 + 0] + g_cagg[n * 4 + 0] * s;
        o[1] = coordp[n * 3 + 1] + g_cagg[n * 4 + 1] * s;
        o[2] = coordp[n * 3 + 2] + g_cagg[n * 4 + 2] * s;
    }
}

// ---------------- host ----------------
extern "C" void kernel_launch(void* const* d_in, const int* in_sizes, int n_in,
                              void* d_out, int out_size) {
    (void)in_sizes; (void)n_in; (void)out_size;
    const float* h     = (const float*)d_in[0];
    const int*   ei    = (const int*)d_in[1];
    const float* coord = (const float*)d_in[2];
    const float* We1   = (const float*)d_in[3];
    const float* be1   = (const float*)d_in[4];
    const float* We2   = (const float*)d_in[5];
    const float* be2   = (const float*)d_in[6];
    const float* Wn1   = (const float*)d_in[7];
    const float* bn1   = (const float*)d_in[8];
    const float* Wn2   = (const float*)d_in[9];
    const float* bn2   = (const float*)d_in[10];
    const float* Wc1   = (const float*)d_in[11];
    const float* bc1   = (const float*)d_in[12];
    const float* Wc2   = (const float*)d_in[13];
    float* out = (float*)d_out;

    cudaFuncSetAttribute(edge_kernel, cudaFuncAttributeMaxDynamicSharedMemorySize, E_SMEM);
    cudaFuncSetAttribute(node_kernel, cudaFuncAttributeMaxDynamicSharedMemorySize, N_SMEM);
    cudaFuncSetAttribute(pre_kernel,  cudaFuncAttributeMaxDynamicSharedMemorySize, P_SMEM);

    void* agg_p = nullptr; void* cagg_p = nullptr;
    cudaGetSymbolAddress(&agg_p, g_agg);
    cudaGetSymbolAddress(&cagg_p, g_cagg);
    cudaMemsetAsync(agg_p, 0, sizeof(float) * (size_t)NN * 256, 0);
    cudaMemsetAsync(cagg_p, 0, sizeof(float) * (size_t)NN * 4, 0);

    __half* we2h; __half* wc1h; __half* wn1h; __half* wn2h;
    cudaGetSymbolAddress((void**)&we2h, g_We2h);
    cudaGetSymbolAddress((void**)&wc1h, g_Wc1h);
    cudaGetSymbolAddress((void**)&wn1h, g_Wn1h);
    cudaGetSymbolAddress((void**)&wn2h, g_Wn2h);

    pack_we1<<<(256 * 512 + 255) / 256, 256>>>(We1);
    pack_half<<<(256 * 256 + 255) / 256, 256>>>(We2, we2h, 256 * 256);
    pack_half<<<(256 * 256 + 255) / 256, 256>>>(Wc1, wc1h, 256 * 256);
    pack_half<<<(256 * 512 + 255) / 256, 256>>>(Wn1, wn1h, 256 * 512);
    pack_half<<<(256 * 256 + 255) / 256, 256>>>(Wn2, wn2h, 256 * 256);
    round_h_kernel<<<(NN * 256 + 255) / 256, 256>>>(h);

    pre_kernel<<<dim3((NN + 127) / 128, 2), 256, P_SMEM>>>();

    edge_kernel<<<NE / 128, 512, E_SMEM>>>(coord, ei, be1, be2, bc1, Wc2);

    round_agg_kernel<<<(NN * 256 + 255) / 256, 256>>>();

    node_kernel<<<(NN + 127) / 128, 512, N_SMEM>>>(h, bn1, bn2, out);
    coord_kernel<<<(NN + 255) / 256, 256>>>(coord, out);
}

// round 12
// speedup vs baseline: 2.5633x; 1.1488x over previous
#include <cuda_runtime.h>
#include <cuda_fp16.h>
#include <cstdint>
#include <cstddef>

#define NN 50000
#define NE 800000

// ---------------- scratch (no allocation allowed) ----------------
__device__ float  g_agg[NN * 256];     // fp32 segment-sum of edge_feat
__device__ __half g_aggh[NN * 256];    // half copy for node GEMM1
__device__ float  g_cagg[NN * 4];      // {sum dx*phi, dy*phi, dz*phi, count}
__device__ __half g_hh[NN * 256];      // half-rounded h
__device__ __half g_P1h[NN * 256];     // h @ We1[:, :256]^T   (half)
__device__ __half g_P2h[NN * 256];     // h @ We1[:, 256:512]^T (half)
__device__ __half g_We1ah[256 * 256];  // [n][k] half, k = 0..255
__device__ __half g_We1bh[256 * 256];  // [n][k] half, k = 256..511
__device__ float  g_w512[256];         // We1[:, 512] (radial weight, fp32)
__device__ __half g_We2h[256 * 256];   // [n][k] half
__device__ __half g_Wc1h[256 * 256];
__device__ __half g_Wn1h[256 * 512];
__device__ __half g_Wn2h[256 * 256];

// ---------------- edge kernel smem (bytes) ----------------
#define E_A2   0         // 128 x 264 halves = 67584
#define E_B    67584     // 2 x 256 x 72 halves = 73728
#define E_RS   141312    // 128 ints
#define E_CS   141824
#define E_CD   142336    // 128 float4
#define E_PHI  144384    // 128 floats
#define E_BE1  144896    // 256 floats
#define E_W512 145920
#define E_BE2  146944
#define E_BC1  147968
#define E_WC2  148992
#define E_SMEM 150016

// ---------------- node kernel smem (512 threads, K=64 chunks) ----------------
#define N_A1   0         // 2 x 128 x 72 halves = 36864
#define N_B    36864     // 2 x 256 x 72 halves = 73728
#define N_A2   110592    // 128 x 264 halves = 67584
#define N_IDX  178176    // 128 ints
#define N_B1   178688    // 256 floats
#define N_B2   179712    // 256 floats
#define N_SMEM 180736

// ---------------- pre kernel smem (256 threads, K=32 chunks) ----------------
#define P_A1   0         // 2 x 128 x 40 halves = 20480
#define P_B    20480     // 2 x 256 x 40 halves = 40960
#define P_IDX  61440
#define P_SMEM 61952

// ---------------- helpers ----------------
__device__ __forceinline__ uint32_t smem_u32(const void* p) {
    uint32_t a;
    asm("{ .reg .u64 t; cvta.to.shared.u64 t, %1; cvt.u32.u64 %0, t; }" : "=r"(a) : "l"(p));
    return a;
}
__device__ __forceinline__ void cpa16(uint32_t s, const void* g) {
    asm volatile("cp.async.cg.shared.global [%0], [%1], 16;" :: "r"(s), "l"(g));
}
__device__ __forceinline__ void cpcommit() { asm volatile("cp.async.commit_group;"); }
__device__ __forceinline__ void cpwait0() { asm volatile("cp.async.wait_group 0;"); }

__device__ __forceinline__ float silu_f(float x) { return x / (1.0f + __expf(-x)); }
__device__ __forceinline__ void red4(float* gp, float x, float y, float z, float w) {
    asm volatile("red.global.add.v4.f32 [%0], {%1,%2,%3,%4};"
                 :: "l"(gp), "f"(x), "f"(y), "f"(z), "f"(w) : "memory");
}

#define MMA_H(c, a, b) \
    asm volatile( \
        "mma.sync.aligned.m16n8k16.row.col.f32.f16.f16.f32 " \
        "{%0,%1,%2,%3},{%4,%5,%6,%7},{%8,%9},{%0,%1,%2,%3};" \
        : "+f"((c)[0]), "+f"((c)[1]), "+f"((c)[2]), "+f"((c)[3]) \
        : "r"((a)[0]), "r"((a)[1]), "r"((a)[2]), "r"((a)[3]), \
          "r"((b)[0]), "r"((b)[1]))

#define LDSM4(r0, r1, r2, r3, addr) \
    asm volatile("ldmatrix.sync.aligned.m8n8.x4.shared.b16 {%0,%1,%2,%3}, [%4];" \
                 : "=r"(r0), "=r"(r1), "=r"(r2), "=r"(r3) : "r"(addr))

// ===== K=64 chunk, warp tile 64x32, ldmatrix loads =====
template <int SA>
__device__ __forceinline__ void gemm_ldsm(uint32_t aAddr, uint32_t bAddr,
                                          float (&c)[4][4][4],
                                          int wm, int wn, int lane) {
    const int arow = wm * 64 + (lane & 15);
    const int kA = ((lane >> 4) & 1) * 8;
    const int bn = wn * 32 + (lane & 7) + ((lane >> 4) & 1) * 8;
    const int kB = ((lane >> 3) & 1) * 8;
#pragma unroll
    for (int s = 0; s < 4; s++) {
        uint32_t a[4][4];
#pragma unroll
        for (int i = 0; i < 4; i++) {
            uint32_t ad = aAddr + (uint32_t)(((arow + i * 16) * SA + s * 16 + kA) * 2);
            LDSM4(a[i][0], a[i][1], a[i][2], a[i][3], ad);
        }
        uint32_t b[4][2];
#pragma unroll
        for (int jp = 0; jp < 2; jp++) {
            uint32_t bd = bAddr + (uint32_t)(((bn + jp * 16) * 72 + s * 16 + kB) * 2);
            LDSM4(b[2 * jp][0], b[2 * jp][1], b[2 * jp + 1][0], b[2 * jp + 1][1], bd);
        }
#pragma unroll
        for (int i = 0; i < 4; i++)
#pragma unroll
            for (int j = 0; j < 4; j++)
                MMA_H(c[i][j], a[i], b[j]);
    }
}

// ===== 256-thread pre kernel path: K=32 chunk, warp tile 64x64 =====
template <int SA>
__device__ __forceinline__ void gemm_chunk_h(const __half* __restrict__ Ac,
                                             const __half* __restrict__ Bc,
                                             float (&c)[4][8][4],
                                             int wm, int wn, int g, int t) {
#pragma unroll
    for (int s = 0; s < 2; s++) {
        int kb = s * 16 + 2 * t;
        uint32_t a[4][4];
#pragma unroll
        for (int i = 0; i < 4; i++) {
            const __half* ap = Ac + (wm * 64 + i * 16 + g) * SA + kb;
            a[i][0] = *(const uint32_t*)(ap);
            a[i][1] = *(const uint32_t*)(ap + 8 * SA);
            a[i][2] = *(const uint32_t*)(ap + 8);
            a[i][3] = *(const uint32_t*)(ap + 8 * SA + 8);
        }
        uint32_t b[8][2];
#pragma unroll
        for (int j = 0; j < 8; j++) {
            const __half* bp = Bc + (wn * 64 + j * 8 + g) * 40 + kb;
            b[j][0] = *(const uint32_t*)(bp);
            b[j][1] = *(const uint32_t*)(bp + 8);
        }
#pragma unroll
        for (int i = 0; i < 4; i++)
#pragma unroll
            for (int j = 0; j < 8; j++)
                MMA_H(c[i][j], a[i], b[j]);
    }
}

__device__ __forceinline__ void init_bias4(float (&c)[4][4][4], const float* bs, int wn, int t) {
#pragma unroll
    for (int j = 0; j < 4; j++) {
        int col = wn * 32 + j * 8 + 2 * t;
        float b0 = bs[col], b1 = bs[col + 1];
#pragma unroll
        for (int i = 0; i < 4; i++) {
            c[i][j][0] = b0; c[i][j][1] = b1; c[i][j][2] = b0; c[i][j][3] = b1;
        }
    }
}

__device__ __forceinline__ void store_silu4(const float (&c)[4][4][4], __half* A2,
                                            int wm, int wn, int g, int t) {
#pragma unroll
    for (int i = 0; i < 4; i++) {
        int r0 = wm * 64 + i * 16 + g;
#pragma unroll
        for (int j = 0; j < 4; j++) {
            int col = wn * 32 + j * 8 + 2 * t;
            *(__half2*)(A2 + r0 * 264 + col) =
                __floats2half2_rn(silu_f(c[i][j][0]), silu_f(c[i][j][1]));
            *(__half2*)(A2 + (r0 + 8) * 264 + col) =
                __floats2half2_rn(silu_f(c[i][j][2]), silu_f(c[i][j][3]));
        }
    }
}

// ---------------- prep kernels ----------------
// Fused weight packing: We1 split + w512, We2, Wc1, Wn1, Wn2. grid 512 x 256.
__global__ void prep_all(const float* __restrict__ We1, const float* __restrict__ We2,
                         const float* __restrict__ Wc1, const float* __restrict__ Wn1,
                         const float* __restrict__ Wn2) {
    int i = blockIdx.x * blockDim.x + threadIdx.x;   // [0, 131072)
    {   // We1: 256 x 512 -> split halves
        int n = i >> 9, k = i & 511;
        __half v = __float2half_rn(We1[n * 513 + k]);
        if (k < 256) g_We1ah[n * 256 + k] = v;
        else         g_We1bh[n * 256 + (k - 256)] = v;
    }
    if (i < 256) g_w512[i] = We1[i * 513 + 512];
    if (i < 65536) {
        g_We2h[i] = __float2half_rn(We2[i]);
        g_Wc1h[i] = __float2half_rn(Wc1[i]);
        g_Wn2h[i] = __float2half_rn(Wn2[i]);
    }
    g_Wn1h[i] = __float2half_rn(Wn1[i]);   // i < 131072 = 256*512
}
__global__ void round_h_kernel(const float* __restrict__ h) {
    int i = blockIdx.x * blockDim.x + threadIdx.x;
    if (i < NN * 256) g_hh[i] = __float2half_rn(h[i]);
}
__global__ void round_agg_kernel() {
    int i = blockIdx.x * blockDim.x + threadIdx.x;
    if (i < NN * 256) g_aggh[i] = __float2half_rn(g_agg[i]);
}

// ---------------- precompute kernel: P{1,2} = h @ We1{a,b}^T (K=256, half out) ----------------
__global__ __launch_bounds__(256, 1) void pre_kernel() {
    extern __shared__ char smem[];
    __half* A1s = (__half*)(smem + P_A1);
    __half* Bsm = (__half*)(smem + P_B);
    int* idx = (int*)(smem + P_IDX);

    const __half* Wh = (blockIdx.y == 0) ? g_We1ah : g_We1bh;
    __half* P = (blockIdx.y == 0) ? g_P1h : g_P2h;

    const int tid = threadIdx.x;
    const int warp = tid >> 5, lane = tid & 31;
    const int wm = warp >> 2, wn = warp & 3, g = lane >> 2, t = lane & 3;
    const int base = blockIdx.x * 128;
    const uint32_t sbase = smem_u32(smem);
    const uint32_t a1u = sbase + P_A1, bu = sbase + P_B;

    if (tid < 128) {
        int n = base + tid;
        idx[tid] = (n < NN) ? n : 0;
    }
    __syncthreads();

    float c[4][8][4];
#pragma unroll
    for (int i = 0; i < 4; i++)
#pragma unroll
        for (int j = 0; j < 8; j++) {
            c[i][j][0] = 0.f; c[i][j][1] = 0.f; c[i][j][2] = 0.f; c[i][j][3] = 0.f;
        }

    auto stageA = [&](int kc, int buf) {
#pragma unroll
        for (int it = 0; it < 2; it++) {
            int v = it * 256 + tid;
            int r = v >> 2, seg = v & 3;
            cpa16(a1u + (uint32_t)(buf * 10240 + r * 80 + seg * 16),
                  g_hh + (size_t)idx[r] * 256 + kc * 32 + seg * 8);
        }
    };
    auto stageB = [&](int kc, int buf) {
#pragma unroll
        for (int it = 0; it < 4; it++) {
            int v = it * 256 + tid;
            int n = v >> 2, seg = v & 3;
            cpa16(bu + (uint32_t)(buf * 20480 + n * 80 + seg * 16),
                  Wh + (size_t)n * 256 + kc * 32 + seg * 8);
        }
    };

    stageA(0, 0); stageB(0, 0); cpcommit();
    for (int kc = 0; kc < 8; kc++) {
        cpwait0();
        __syncthreads();
        if (kc + 1 < 8) { stageA(kc + 1, (kc + 1) & 1); stageB(kc + 1, (kc + 1) & 1); cpcommit(); }
        gemm_chunk_h<40>(A1s + (kc & 1) * 5120, Bsm + (kc & 1) * 10240, c, wm, wn, g, t);
    }

#pragma unroll
    for (int i = 0; i < 4; i++) {
        int r0 = wm * 64 + i * 16 + g;
        int n0 = base + r0, n1 = base + r0 + 8;
#pragma unroll
        for (int j = 0; j < 8; j++) {
            int col = wn * 64 + j * 8 + 2 * t;
            if (n0 < NN)
                *(__half2*)(P + (size_t)n0 * 256 + col) = __floats2half2_rn(c[i][j][0], c[i][j][1]);
            if (n1 < NN)
                *(__half2*)(P + (size_t)n1 * 256 + col) = __floats2half2_rn(c[i][j][2], c[i][j][3]);
        }
    }
}

// ---------------- edge kernel (512 threads, K=64 chunks, ldmatrix) ----------------
__global__ __launch_bounds__(512, 1) void edge_kernel(
    const float* __restrict__ coordp, const int* __restrict__ ei,
    const float* __restrict__ be1, const float* __restrict__ be2,
    const float* __restrict__ bc1, const float* __restrict__ wc2) {
    extern __shared__ char smem[];
    __half* A2  = (__half*)(smem + E_A2);
    int* rs = (int*)(smem + E_RS);
    int* cs = (int*)(smem + E_CS);
    float4* cd = (float4*)(smem + E_CD);
    float* phis = (float*)(smem + E_PHI);
    float* be1s = (float*)(smem + E_BE1);
    float* w512s = (float*)(smem + E_W512);
    float* be2s = (float*)(smem + E_BE2);
    float* bc1s = (float*)(smem + E_BC1);
    float* wc2s = (float*)(smem + E_WC2);

    const int tid = threadIdx.x;
    const int warp = tid >> 5, lane = tid & 31;
    const int wm = warp >> 3, wn = warp & 7, g = lane >> 2, t = lane & 3;
    const int ebase = blockIdx.x * 128;
    const uint32_t sbase = smem_u32(smem);
    const uint32_t a2u = sbase + E_A2, bu = sbase + E_B;

    if (tid < 128) {
        int r = ei[ebase + tid], c = ei[NE + ebase + tid];
        rs[tid] = r; cs[tid] = c;
        float dx = coordp[r * 3 + 0] - coordp[c * 3 + 0];
        float dy = coordp[r * 3 + 1] - coordp[c * 3 + 1];
        float dz = coordp[r * 3 + 2] - coordp[c * 3 + 2];
        cd[tid] = make_float4(dx, dy, dz, dx * dx + dy * dy + dz * dz);
        phis[tid] = 0.f;
    }
    if (tid < 256) {
        be1s[tid] = be1[tid]; w512s[tid] = g_w512[tid];
        be2s[tid] = be2[tid]; bc1s[tid] = bc1[tid]; wc2s[tid] = wc2[tid];
    }
    __syncthreads();

    auto stageB = [&](const __half* __restrict__ Wh, int kc, int buf) {
#pragma unroll
        for (int it = 0; it < 4; it++) {
            int v = it * 512 + tid;
            int n = v >> 3, seg = v & 7;
            cpa16(bu + (uint32_t)(buf * 36864 + n * 144 + seg * 16),
                  Wh + (size_t)n * 256 + kc * 64 + seg * 8);
        }
    };

    stageB(g_We2h, 0, 0); cpcommit();

    // prologue: A2 = half(silu(P1[row] + P2[col] + radial*w512 + be1)), half inputs
#pragma unroll
    for (int it = 0; it < 8; it++) {
        int v = it * 512 + tid;
        int r = v >> 5, c8 = (v & 31) << 3;
        uint4 pa = *(const uint4*)(g_P1h + (size_t)rs[r] * 256 + c8);
        uint4 pb = *(const uint4*)(g_P2h + (size_t)cs[r] * 256 + c8);
        float rad = cd[r].w;
        const uint32_t* ua = (const uint32_t*)&pa;
        const uint32_t* ub = (const uint32_t*)&pb;
        uint32_t outw[4];
#pragma unroll
        for (int q = 0; q < 4; q++) {
            float2 fa = __half22float2(*(const __half2*)&ua[q]);
            float2 fb = __half22float2(*(const __half2*)&ub[q]);
            int col = c8 + q * 2;
            float x0 = fa.x + fb.x + rad * w512s[col]     + be1s[col];
            float x1 = fa.y + fb.y + rad * w512s[col + 1] + be1s[col + 1];
            __half2 o = __floats2half2_rn(silu_f(x0), silu_f(x1));
            outw[q] = *(const uint32_t*)&o;
        }
        *(uint4*)(A2 + r * 264 + c8) = *(const uint4*)outw;
    }

    float c[4][4][4];

    // ---- GEMM2: m @ We2^T (K=256, 4 chunks of 64) ----
    init_bias4(c, be2s, wn, t);
    for (int kc = 0; kc < 4; kc++) {
        cpwait0();
        __syncthreads();
        if (kc + 1 < 4) { stageB(g_We2h, kc + 1, (kc + 1) & 1); cpcommit(); }
        gemm_ldsm<264>(a2u + kc * 128, bu + (kc & 1) * 36864, c, wm, wn, lane);
    }
    __syncthreads();
    store_silu4(c, A2, wm, wn, g, t);   // A2 = edge_feat (half)
    stageB(g_Wc1h, 0, 0); cpcommit();
    __syncthreads();                    // A2 fully written

    // feature aggregation issued EARLY: red4s drain behind GEMM3's mma work
#pragma unroll
    for (int it = 0; it < 16; it++) {
        int v = it * 512 + tid;
        int r = v >> 6, c4 = (v & 63) << 2;
        __half2 p0 = *(const __half2*)(A2 + r * 264 + c4);
        __half2 p1 = *(const __half2*)(A2 + r * 264 + c4 + 2);
        red4(&g_agg[(size_t)rs[r] * 256 + c4],
             __low2float(p0), __high2float(p0), __low2float(p1), __high2float(p1));
    }

    // ---- GEMM3: edge_feat @ Wc1^T (K=256, 4 chunks) ----
    init_bias4(c, bc1s, wn, t);
    for (int kc = 0; kc < 4; kc++) {
        cpwait0();
        __syncthreads();
        if (kc + 1 < 4) { stageB(g_Wc1h, kc + 1, (kc + 1) & 1); cpcommit(); }
        gemm_ldsm<264>(a2u + kc * 128, bu + (kc & 1) * 36864, c, wm, wn, lane);
    }

    // phi_x[e] = silu(C3) . wc2  (fp32)
    {
        float pr[8];
#pragma unroll
        for (int k = 0; k < 8; k++) pr[k] = 0.f;
#pragma unroll
        for (int i = 0; i < 4; i++)
#pragma unroll
            for (int j = 0; j < 4; j++) {
                int col = wn * 32 + j * 8 + 2 * t;
                float w0 = wc2s[col], w1 = wc2s[col + 1];
                pr[i * 2]     += silu_f(c[i][j][0]) * w0 + silu_f(c[i][j][1]) * w1;
                pr[i * 2 + 1] += silu_f(c[i][j][2]) * w0 + silu_f(c[i][j][3]) * w1;
            }
#pragma unroll
        for (int k = 0; k < 8; k++) {
            pr[k] += __shfl_xor_sync(0xffffffffu, pr[k], 1);
            pr[k] += __shfl_xor_sync(0xffffffffu, pr[k], 2);
        }
        if (t == 0) {
#pragma unroll
            for (int i = 0; i < 4; i++) {
                atomicAdd(&phis[wm * 64 + i * 16 + g], pr[i * 2]);
                atomicAdd(&phis[wm * 64 + i * 16 + g + 8], pr[i * 2 + 1]);
            }
        }
    }
    __syncthreads();

    // coord aggregation
    if (tid < 128) {
        float4 d = cd[tid];
        float p = phis[tid];
        red4(&g_cagg[(size_t)rs[tid] * 4], d.x * p, d.y * p, d.z * p, 1.0f);
    }
}

// ---------------- node kernel (512 threads, K=64 chunks, ldmatrix) ----------------
__global__ __launch_bounds__(512, 1) void node_kernel(
    const float* __restrict__ h, const float* __restrict__ bn1,
    const float* __restrict__ bn2, float* __restrict__ out) {
    extern __shared__ char smem[];
    __half* A2  = (__half*)(smem + N_A2);
    int* idx = (int*)(smem + N_IDX);
    float* b1s = (float*)(smem + N_B1);
    float* b2s = (float*)(smem + N_B2);

    const int tid = threadIdx.x;
    const int warp = tid >> 5, lane = tid & 31;
    const int wm = warp >> 3, wn = warp & 7, g = lane >> 2, t = lane & 3;
    const int base = blockIdx.x * 128;
    const uint32_t sbase = smem_u32(smem);
    const uint32_t a1u = sbase + N_A1, bu = sbase + N_B, a2u = sbase + N_A2;

    if (tid < 128) {
        int n = base + tid;
        idx[tid] = (n < NN) ? n : 0;
    }
    if (tid < 256) { b1s[tid] = bn1[tid]; b2s[tid] = bn2[tid]; }
    __syncthreads();

    auto stageA = [&](int kc, int buf) {
        const __half* basep = (kc < 4) ? g_hh : g_aggh;
        int koff = (kc & 3) * 64;
#pragma unroll
        for (int it = 0; it < 2; it++) {
            int v = it * 512 + tid;
            int r = v >> 3, seg = v & 7;
            cpa16(a1u + (uint32_t)(buf * 18432 + r * 144 + seg * 16),
                  basep + (size_t)idx[r] * 256 + koff + seg * 8);
        }
    };
    auto stageB = [&](const __half* __restrict__ Wh, int kstride, int kc, int buf) {
#pragma unroll
        for (int it = 0; it < 4; it++) {
            int v = it * 512 + tid;
            int n = v >> 3, seg = v & 7;
            cpa16(bu + (uint32_t)(buf * 36864 + n * 144 + seg * 16),
                  Wh + (size_t)n * kstride + kc * 64 + seg * 8);
        }
    };

    float c[4][4][4];

    // GEMM1: [h | agg] @ Wn1^T (K=512, 8 chunks of 64)
    init_bias4(c, b1s, wn, t);
    stageA(0, 0); stageB(g_Wn1h, 512, 0, 0); cpcommit();
    for (int kc = 0; kc < 8; kc++) {
        cpwait0();
        __syncthreads();
        if (kc + 1 < 8) {
            stageA(kc + 1, (kc + 1) & 1);
            stageB(g_Wn1h, 512, kc + 1, (kc + 1) & 1);
            cpcommit();
        }
        gemm_ldsm<72>(a1u + (kc & 1) * 18432, bu + (kc & 1) * 36864, c, wm, wn, lane);
    }
    __syncthreads();
    store_silu4(c, A2, wm, wn, g, t);
    stageB(g_Wn2h, 256, 0, 0); cpcommit();

    // GEMM2: @ Wn2^T (K=256, 4 chunks), + bn2 + residual h
    init_bias4(c, b2s, wn, t);
    for (int kc = 0; kc < 4; kc++) {
        cpwait0();
        __syncthreads();
        if (kc + 1 < 4) { stageB(g_Wn2h, 256, kc + 1, (kc + 1) & 1); cpcommit(); }
        gemm_ldsm<264>(a2u + kc * 128, bu + (kc & 1) * 36864, c, wm, wn, lane);
    }
#pragma unroll
    for (int i = 0; i < 4; i++) {
        int r0 = wm * 64 + i * 16 + g;
        int n0 = base + r0, n1 = base + r0 + 8;
#pragma unroll
        for (int j = 0; j < 4; j++) {
            int col = wn * 32 + j * 8 + 2 * t;
            if (n0 < NN) {
                out[(size_t)n0 * 256 + col]     = c[i][j][0] + h[(size_t)n0 * 256 + col];
                out[(size_t)n0 * 256 + col + 1] = c[i][j][1] + h[(size_t)n0 * 256 + col + 1];
            }
            if (n1 < NN) {
                out[(size_t)n1 * 256 + col]     = c[i][j][2] + h[(size_t)n1 * 256 + col];
                out[(size_t)n1 * 256 + col + 1] = c[i][j][3] + h[(size_t)n1 * 256 + col + 1];
            }
        }
    }
}

// ---------------- coord finish ----------------
__global__ void coord_kernel(const float* __restrict__ coordp, float* __restrict__ out) {
    int n = blockIdx.x * blockDim.x + threadIdx.x;
    if (n < NN) {
        float cnt = g_cagg[n * 4 + 3];
        float s = 1.0f / fmaxf(cnt, 1.0f);
        float* o = out + (size_t)NN * 256 + (size_t)n * 3;
        o[0] = coordp[n * 3 + 0] + g_cagg[n * 4 + 0] * s;
        o[1] = coordp[n * 3 + 1] + g_cagg[n * 4 + 1] * s;
        o[2] = coordp[n * 3 + 2] + g_cagg[n * 4 + 2] * s;
    }
}

// ---------------- host ----------------
extern "C" void kernel_launch(void* const* d_in, const int* in_sizes, int n_in,
                              void* d_out, int out_size) {
    (void)in_sizes; (void)n_in; (void)out_size;
    const float* h     = (const float*)d_in[0];
    const int*   ei    = (const int*)d_in[1];
    const float* coord = (const float*)d_in[2];
    const float* We1   = (const float*)d_in[3];
    const float* be1   = (const float*)d_in[4];
    const float* We2   = (const float*)d_in[5];
    const float* be2   = (const float*)d_in[6];
    const float* Wn1   = (const float*)d_in[7];
    const float* bn1   = (const float*)d_in[8];
    const float* Wn2   = (const float*)d_in[9];
    const float* bn2   = (const float*)d_in[10];
    const float* Wc1   = (const float*)d_in[11];
    const float* bc1   = (const float*)d_in[12];
    const float* Wc2   = (const float*)d_in[13];
    float* out = (float*)d_out;

    cudaFuncSetAttribute(edge_kernel, cudaFuncAttributeMaxDynamicSharedMemorySize, E_SMEM);
    cudaFuncSetAttribute(node_kernel, cudaFuncAttributeMaxDynamicSharedMemorySize, N_SMEM);
    cudaFuncSetAttribute(pre_kernel,  cudaFuncAttributeMaxDynamicSharedMemorySize, P_SMEM);

    void* agg_p = nullptr; void* cagg_p = nullptr;
    cudaGetSymbolAddress(&agg_p, g_agg);
    cudaGetSymbolAddress(&cagg_p, g_cagg);

    // Launch order chosen so edge_kernel is the 6th launch (ncu -s 5 -c 1 captures it):
    // memset(1), memset(2), prep_all(3), round_h(4), pre(5), edge(6)
    cudaMemsetAsync(agg_p, 0, sizeof(float) * (size_t)NN * 256, 0);
    cudaMemsetAsync(cagg_p, 0, sizeof(float) * (size_t)NN * 4, 0);

    prep_all<<<512, 256>>>(We1, We2, Wc1, Wn1, Wn2);
    round_h_kernel<<<(NN * 256 + 255) / 256, 256>>>(h);

    pre_kernel<<<dim3((NN + 127) / 128, 2), 256, P_SMEM>>>();

    edge_kernel<<<NE / 128, 512, E_SMEM>>>(coord, ei, be1, be2, bc1, Wc2);

    round_agg_kernel<<<(NN * 256 + 255) / 256, 256>>>();

    node_kernel<<<(NN + 127) / 128, 512, N_SMEM>>>(h, bn1, bn2, out);
    coord_kernel<<<(NN + 255) / 256, 256>>>(coord, out);
}